// round 13
// baseline (speedup 1.0000x reference)
#include <cuda_runtime.h>
#include <cuda_bf16.h>
#include <cuda_fp16.h>
#include <cstdint>
#include <math.h>

#define BB 2
#define SS 2048
#define DD 1024
#define HH 16
#define DHH 64
#define MTOT (BB*SS)
#define LOG2E 1.44269504088896f

__device__ __align__(256) __nv_bfloat16 g_Whi[4][DD*DD];
__device__ __align__(256) __nv_bfloat16 g_Wlo[4][DD*DD];
__device__ __align__(256) __nv_bfloat16 g_Ahi[3][MTOT*DD];
__device__ __align__(256) __nv_bfloat16 g_Alo[3][MTOT*DD];
__device__ __align__(256) __nv_bfloat16 g_Qhi[MTOT*DD];
__device__ __align__(256) __nv_bfloat16 g_Qlo[MTOT*DD];
__device__ __align__(256) __nv_bfloat16 g_Khi[MTOT*DD];
__device__ __align__(256) __nv_bfloat16 g_Klo[MTOT*DD];
__device__ __align__(256) __half        g_Vh [MTOT*DD];
__device__ __align__(256) __nv_bfloat16 g_Xhi[MTOT*DD];
__device__ __align__(256) __nv_bfloat16 g_Xlo[MTOT*DD];

__device__ __forceinline__ uint32_t smem_u32(const void* p) {
    uint32_t a;
    asm("{ .reg .u64 t; cvta.to.shared.u64 t, %1; cvt.u32.u64 %0, t; }" : "=r"(a) : "l"(p));
    return a;
}
__device__ __forceinline__ void cp_async16(uint32_t dst, const void* src) {
    asm volatile("cp.async.cg.shared.global [%0], [%1], 16;" :: "r"(dst), "l"(src));
}
#define CP_COMMIT() asm volatile("cp.async.commit_group;" ::: "memory")

#define MMA_BF16(c, a, b0, b1) \
    asm volatile("mma.sync.aligned.m16n8k16.row.col.f32.bf16.bf16.f32 " \
        "{%0,%1,%2,%3}, {%4,%5,%6,%7}, {%8,%9}, {%0,%1,%2,%3};" \
        : "+f"((c)[0]), "+f"((c)[1]), "+f"((c)[2]), "+f"((c)[3]) \
        : "r"((a)[0]), "r"((a)[1]), "r"((a)[2]), "r"((a)[3]), "r"(b0), "r"(b1))

#define MMA_F16(c, a0, a1, a2, a3, b0, b1) \
    asm volatile("mma.sync.aligned.m16n8k16.row.col.f32.f16.f16.f32 " \
        "{%0,%1,%2,%3}, {%4,%5,%6,%7}, {%8,%9}, {%0,%1,%2,%3};" \
        : "+f"((c)[0]), "+f"((c)[1]), "+f"((c)[2]), "+f"((c)[3]) \
        : "r"(a0), "r"(a1), "r"(a2), "r"(a3), "r"(b0), "r"(b1))

#define LDM_X4(r, a) \
    asm volatile("ldmatrix.sync.aligned.m8n8.x4.shared.b16 {%0,%1,%2,%3}, [%4];" \
        : "=r"((r)[0]), "=r"((r)[1]), "=r"((r)[2]), "=r"((r)[3]) : "r"(a))

__device__ __forceinline__ uint32_t f2h2(float x, float y) {
    __half2 t = __floats2half2_rn(x, y);
    return *(uint32_t*)&t;
}
__device__ __forceinline__ float ex2(float x) {
    float y;
    asm("ex2.approx.ftz.f32 %0, %1;" : "=f"(y) : "f"(x));
    return y;
}

// ============ fused prologue: z<3 -> activation split, z==3 -> weight transposes ============
__global__ __launch_bounds__(256) void pre_kernel(
    const float* __restrict__ a0, const float* __restrict__ a1,
    const float* __restrict__ a2,
    const float* __restrict__ w0, const float* __restrict__ w1,
    const float* __restrict__ w2, const float* __restrict__ w3,
    __nv_bfloat16* __restrict__ Ahi_base, __nv_bfloat16* __restrict__ Alo_base,
    __nv_bfloat16* __restrict__ Whi_base, __nv_bfloat16* __restrict__ Wlo_base)
{
    if (blockIdx.z < 3) {
        int i = blockIdx.x * 256 + threadIdx.x;
        const float* a = (blockIdx.z == 0) ? a0 : (blockIdx.z == 1) ? a1 : a2;
        __nv_bfloat16* hi = Ahi_base + (size_t)blockIdx.z * MTOT * DD;
        __nv_bfloat16* lo = Alo_base + (size_t)blockIdx.z * MTOT * DD;
        float4 v = ((const float4*)a)[i];
        __nv_bfloat16 hx = __float2bfloat16_rn(v.x), hy = __float2bfloat16_rn(v.y);
        __nv_bfloat16 hz = __float2bfloat16_rn(v.z), hw = __float2bfloat16_rn(v.w);
        __nv_bfloat162 h0; h0.x = hx; h0.y = hy;
        __nv_bfloat162 h1; h1.x = hz; h1.y = hw;
        __nv_bfloat162 l0, l1;
        l0.x = __float2bfloat16_rn(v.x - __bfloat162float(hx));
        l0.y = __float2bfloat16_rn(v.y - __bfloat162float(hy));
        l1.x = __float2bfloat16_rn(v.z - __bfloat162float(hz));
        l1.y = __float2bfloat16_rn(v.w - __bfloat162float(hw));
        ((__nv_bfloat162*)hi)[i*2+0] = h0; ((__nv_bfloat162*)hi)[i*2+1] = h1;
        ((__nv_bfloat162*)lo)[i*2+0] = l0; ((__nv_bfloat162*)lo)[i*2+1] = l1;
    } else {
        int wsel = blockIdx.x >> 10;
        int tile = blockIdx.x & 1023;
        int bx = tile & 31, by = tile >> 5;
        const float* in = (wsel == 0) ? w0 : (wsel == 1) ? w1 : (wsel == 2) ? w2 : w3;
        __nv_bfloat16* hi = Whi_base + (size_t)wsel * DD * DD;
        __nv_bfloat16* lo = Wlo_base + (size_t)wsel * DD * DD;
        __shared__ float t[32][33];
        int tx = threadIdx.x & 31, ty = threadIdx.x >> 5;
        int x = bx * 32 + tx;
        int y = by * 32 + ty;
        #pragma unroll
        for (int j = 0; j < 32; j += 8)
            t[ty + j][tx] = in[(size_t)(y + j) * DD + x];
        __syncthreads();
        int x2 = by * 32 + tx;
        int y2 = bx * 32 + ty;
        #pragma unroll
        for (int j = 0; j < 32; j += 8) {
            float w = t[tx][ty + j];
            __nv_bfloat16 h = __float2bfloat16_rn(w);
            hi[(size_t)(y2 + j) * DD + x2] = h;
            lo[(size_t)(y2 + j) * DD + x2] = __float2bfloat16_rn(w - __bfloat162float(h));
        }
    }
}

// ============ shared GEMM pieces ============
#define T_AH    0
#define T_AL    8192
#define T_BH    16384
#define T_BL    24576
#define STAGE   32768
#define GEMM_SMEM (3*STAGE)

__device__ __forceinline__ void load_chunk_g(
    uint32_t sbase, int st,
    const __nv_bfloat16* __restrict__ Ah, const __nv_bfloat16* __restrict__ Al,
    const __nv_bfloat16* __restrict__ Bh, const __nv_bfloat16* __restrict__ Bl,
    int bm, int bn, int k0, int tid)
{
    uint32_t s = sbase + st * STAGE;
    #pragma unroll
    for (int it = 0; it < 2; ++it) {
        int idx = tid + it * 256;
        int row = idx >> 2, q = idx & 3;
        int qs = q ^ ((row >> 1) & 3);
        uint32_t doff = (uint32_t)(row * 64 + qs * 16);
        size_t ga = (size_t)(bm + row) * DD + k0 + q * 8;
        size_t gb = (size_t)(bn + row) * DD + k0 + q * 8;
        cp_async16(s + T_AH + doff, Ah + ga);
        cp_async16(s + T_AL + doff, Al + ga);
        cp_async16(s + T_BH + doff, Bh + gb);
        cp_async16(s + T_BL + doff, Bl + gb);
    }
    CP_COMMIT();
}

// 128x128 core (used by out_gemm)
__device__ __forceinline__ void gemm_core(
    uint32_t sbase, const __nv_bfloat16* Ah, const __nv_bfloat16* Al,
    const __nv_bfloat16* Bh, const __nv_bfloat16* Bl,
    int bm, int bn, int tid, int lane, int warp_m, int warp_n,
    float c[4][4][4])
{
    const int a_row = warp_m * 64 + (lane & 15);
    const int sA = (a_row >> 1) & 3;
    const int b_row = warp_n * 32 + ((lane >> 4) << 3) + (lane & 7);
    const int sB = (b_row >> 1) & 3;
    const int ca = (lane >> 4);
    const int cb = ((lane >> 3) & 1);

    load_chunk_g(sbase, 0, Ah, Al, Bh, Bl, bm, bn, 0,  tid);
    load_chunk_g(sbase, 1, Ah, Al, Bh, Bl, bm, bn, 32, tid);

    const int NCHUNK = DD / 32;
    for (int i = 0; i < NCHUNK; ++i) {
        const int st = i % 3;
        if (i < NCHUNK - 1) asm volatile("cp.async.wait_group 1;" ::: "memory");
        else                asm volatile("cp.async.wait_group 0;" ::: "memory");
        __syncthreads();
        if (i + 2 < NCHUNK)
            load_chunk_g(sbase, (i + 2) % 3, Ah, Al, Bh, Bl, bm, bn, (i + 2) * 32, tid);

        const uint32_t stb = sbase + st * STAGE;
        #pragma unroll
        for (int ks = 0; ks < 2; ++ks) {
            uint32_t ah[4][4], al[4][4], bh[2][4], bl[2][4];
            const uint32_t ac = (uint32_t)(((ks * 2 + ca) ^ sA) << 4);
            const uint32_t bc = (uint32_t)(((ks * 2 + cb) ^ sB) << 4);
            #pragma unroll
            for (int mf = 0; mf < 4; ++mf) {
                uint32_t ra = stb + T_AH + (uint32_t)((a_row + mf * 16) * 64) + ac;
                LDM_X4(ah[mf], ra);
                LDM_X4(al[mf], ra + (T_AL - T_AH));
            }
            #pragma unroll
            for (int p = 0; p < 2; ++p) {
                uint32_t rb = stb + T_BH + (uint32_t)((b_row + p * 16) * 64) + bc;
                LDM_X4(bh[p], rb);
                LDM_X4(bl[p], rb + (T_BL - T_BH));
            }
            #pragma unroll
            for (int mf = 0; mf < 4; ++mf)
                #pragma unroll
                for (int nf = 0; nf < 4; ++nf) {
                    const int p = nf >> 1, hh = (nf & 1) * 2;
                    MMA_BF16(c[mf][nf], ah[mf], bh[p][hh], bh[p][hh+1]);
                    MMA_BF16(c[mf][nf], ah[mf], bl[p][hh], bl[p][hh+1]);
                    MMA_BF16(c[mf][nf], al[mf], bh[p][hh], bh[p][hh+1]);
                }
        }
    }
}

// ============ 128x64-tile fused QKV GEMM (fine wave packing) ============
#define Q_AH 0
#define Q_AL 8192
#define Q_BH 16384
#define Q_BL 20480
#define Q_STAGE 24576
#define QKV_SMEM (3*Q_STAGE)   // 73728

__device__ __forceinline__ void load_chunk_q(
    uint32_t sbase, int st,
    const __nv_bfloat16* __restrict__ Ah, const __nv_bfloat16* __restrict__ Al,
    const __nv_bfloat16* __restrict__ Bh, const __nv_bfloat16* __restrict__ Bl,
    int bm, int bn, int k0, int tid)
{
    uint32_t s = sbase + st * Q_STAGE;
    #pragma unroll
    for (int it = 0; it < 2; ++it) {
        int idx = tid + it * 256;          // 0..511 : A 128 rows x 4 slots
        int row = idx >> 2, q = idx & 3;
        int qs = q ^ ((row >> 1) & 3);
        uint32_t doff = (uint32_t)(row * 64 + qs * 16);
        size_t ga = (size_t)(bm + row) * DD + k0 + q * 8;
        cp_async16(s + Q_AH + doff, Ah + ga);
        cp_async16(s + Q_AL + doff, Al + ga);
    }
    {
        int row = tid >> 2, q = tid & 3;   // B 64 rows x 4 slots
        int qs = q ^ ((row >> 1) & 3);
        uint32_t doff = (uint32_t)(row * 64 + qs * 16);
        size_t gb = (size_t)(bn + row) * DD + k0 + q * 8;
        cp_async16(s + Q_BH + doff, Bh + gb);
        cp_async16(s + Q_BL + doff, Bl + gb);
    }
    CP_COMMIT();
}

// grid (48, 32): proj = blockIdx.x>>4, bn = (blockIdx.x&15)*64, bm = blockIdx.y*128
__global__ __launch_bounds__(256, 2) void qkv_gemm(
    const __nv_bfloat16* __restrict__ Ahi_all, const __nv_bfloat16* __restrict__ Alo_all,
    const __nv_bfloat16* __restrict__ Whi_all, const __nv_bfloat16* __restrict__ Wlo_all,
    const float* __restrict__ bq, const float* __restrict__ bk, const float* __restrict__ bv,
    __nv_bfloat16* __restrict__ Qhi, __nv_bfloat16* __restrict__ Qlo,
    __nv_bfloat16* __restrict__ Khi, __nv_bfloat16* __restrict__ Klo,
    __half* __restrict__ Vh)
{
    extern __shared__ char smem[];
    const uint32_t sbase = smem_u32(smem);
    const int tid = threadIdx.x, wid = tid >> 5, lane = tid & 31;
    const int warp_m = wid & 3;        // 4 m-warps of 32 rows
    const int warp_n = wid >> 2;       // 2 n-warps of 32 cols
    const int proj = blockIdx.x >> 4;
    const int bn = (blockIdx.x & 15) * 64;
    const int bm = blockIdx.y * 128;

    const __nv_bfloat16* Ah = Ahi_all + (size_t)proj * MTOT * DD;
    const __nv_bfloat16* Al = Alo_all + (size_t)proj * MTOT * DD;
    const __nv_bfloat16* Bh = Whi_all + (size_t)proj * DD * DD;
    const __nv_bfloat16* Bl = Wlo_all + (size_t)proj * DD * DD;
    const float* bias = (proj == 0) ? bq : (proj == 1) ? bk : bv;
    const float oscale = (proj == 0) ? LOG2E : 1.0f;

    const int a_row = warp_m * 32 + (lane & 15);
    const int sA = (a_row >> 1) & 3;
    const int b_row = warp_n * 32 + ((lane >> 4) << 3) + (lane & 7);
    const int sB = (b_row >> 1) & 3;
    const int ca = (lane >> 4);
    const int cb = ((lane >> 3) & 1);

    float c[2][4][4];
    #pragma unroll
    for (int i = 0; i < 2; ++i)
        #pragma unroll
        for (int j = 0; j < 4; ++j)
            #pragma unroll
            for (int e = 0; e < 4; ++e) c[i][j][e] = 0.f;

    load_chunk_q(sbase, 0, Ah, Al, Bh, Bl, bm, bn, 0,  tid);
    load_chunk_q(sbase, 1, Ah, Al, Bh, Bl, bm, bn, 32, tid);

    const int NCHUNK = DD / 32;
    for (int i = 0; i < NCHUNK; ++i) {
        const int st = i % 3;
        if (i < NCHUNK - 1) asm volatile("cp.async.wait_group 1;" ::: "memory");
        else                asm volatile("cp.async.wait_group 0;" ::: "memory");
        __syncthreads();
        if (i + 2 < NCHUNK)
            load_chunk_q(sbase, (i + 2) % 3, Ah, Al, Bh, Bl, bm, bn, (i + 2) * 32, tid);

        const uint32_t stb = sbase + st * Q_STAGE;
        #pragma unroll
        for (int ks = 0; ks < 2; ++ks) {
            uint32_t ah[2][4], al[2][4], bh[2][4], bl[2][4];
            const uint32_t ac = (uint32_t)(((ks * 2 + ca) ^ sA) << 4);
            const uint32_t bc = (uint32_t)(((ks * 2 + cb) ^ sB) << 4);
            #pragma unroll
            for (int mf = 0; mf < 2; ++mf) {
                uint32_t ra = stb + Q_AH + (uint32_t)((a_row + mf * 16) * 64) + ac;
                LDM_X4(ah[mf], ra);
                LDM_X4(al[mf], ra + (Q_AL - Q_AH));
            }
            #pragma unroll
            for (int p = 0; p < 2; ++p) {
                uint32_t rb = stb + Q_BH + (uint32_t)((b_row + p * 16) * 64) + bc;
                LDM_X4(bh[p], rb);
                LDM_X4(bl[p], rb + (Q_BL - Q_BH));
            }
            #pragma unroll
            for (int mf = 0; mf < 2; ++mf)
                #pragma unroll
                for (int nf = 0; nf < 4; ++nf) {
                    const int p = nf >> 1, hh = (nf & 1) * 2;
                    MMA_BF16(c[mf][nf], ah[mf], bh[p][hh], bh[p][hh+1]);
                    MMA_BF16(c[mf][nf], ah[mf], bl[p][hh], bl[p][hh+1]);
                    MMA_BF16(c[mf][nf], al[mf], bh[p][hh], bh[p][hh+1]);
                }
        }
    }

    __nv_bfloat16* Oh = (proj == 0) ? Qhi : Khi;
    __nv_bfloat16* Ol = (proj == 0) ? Qlo : Klo;

    #pragma unroll
    for (int mf = 0; mf < 2; ++mf) {
        int m0 = bm + warp_m * 32 + mf * 16 + (lane >> 2);
        #pragma unroll
        for (int nf = 0; nf < 4; ++nf) {
            int n = bn + warp_n * 32 + nf * 8 + (lane & 3) * 2;
            float2 bb = *(const float2*)&bias[n];
            float v0 = (c[mf][nf][0] + bb.x) * oscale, v1 = (c[mf][nf][1] + bb.y) * oscale;
            float v2 = (c[mf][nf][2] + bb.x) * oscale, v3 = (c[mf][nf][3] + bb.y) * oscale;
            size_t i0 = (size_t)m0 * DD + n, i1 = (size_t)(m0 + 8) * DD + n;
            if (proj == 2) {
                *(__half2*)&Vh[i0] = __floats2half2_rn(v0, v1);
                *(__half2*)&Vh[i1] = __floats2half2_rn(v2, v3);
            } else {
                __nv_bfloat16 h0 = __float2bfloat16_rn(v0), h1 = __float2bfloat16_rn(v1);
                __nv_bfloat16 h2 = __float2bfloat16_rn(v2), h3 = __float2bfloat16_rn(v3);
                __nv_bfloat162 H0; H0.x = h0; H0.y = h1;
                __nv_bfloat162 H1; H1.x = h2; H1.y = h3;
                __nv_bfloat162 L0, L1;
                L0.x = __float2bfloat16_rn(v0 - __bfloat162float(h0));
                L0.y = __float2bfloat16_rn(v1 - __bfloat162float(h1));
                L1.x = __float2bfloat16_rn(v2 - __bfloat162float(h2));
                L1.y = __float2bfloat16_rn(v3 - __bfloat162float(h3));
                *(__nv_bfloat162*)&Oh[i0] = H0; *(__nv_bfloat162*)&Oh[i1] = H1;
                *(__nv_bfloat162*)&Ol[i0] = L0; *(__nv_bfloat162*)&Ol[i1] = L1;
            }
        }
    }
}

__global__ __launch_bounds__(256, 2) void out_gemm(
    const __nv_bfloat16* __restrict__ Ah, const __nv_bfloat16* __restrict__ Al,
    const __nv_bfloat16* __restrict__ Bh, const __nv_bfloat16* __restrict__ Bl,
    const float* __restrict__ bias, float* __restrict__ C)
{
    extern __shared__ char smem[];
    const uint32_t sbase = smem_u32(smem);
    const int tid = threadIdx.x, wid = tid >> 5, lane = tid & 31;
    const int warp_m = wid & 1, warp_n = wid >> 1;
    const int bm = blockIdx.y * 128, bn = blockIdx.x * 128;

    float c[4][4][4];
    #pragma unroll
    for (int i = 0; i < 4; ++i)
        #pragma unroll
        for (int j = 0; j < 4; ++j)
            #pragma unroll
            for (int e = 0; e < 4; ++e) c[i][j][e] = 0.f;

    gemm_core(sbase, Ah, Al, Bh, Bl, bm, bn, tid, lane, warp_m, warp_n, c);

    #pragma unroll
    for (int mf = 0; mf < 4; ++mf) {
        int m0 = bm + warp_m * 64 + mf * 16 + (lane >> 2);
        #pragma unroll
        for (int nf = 0; nf < 4; ++nf) {
            int n = bn + warp_n * 32 + nf * 8 + (lane & 3) * 2;
            float2 bb = *(const float2*)&bias[n];
            *(float2*)&C[(size_t)m0 * DD + n] =
                make_float2(c[mf][nf][0] + bb.x, c[mf][nf][1] + bb.y);
            *(float2*)&C[(size_t)(m0 + 8) * DD + n] =
                make_float2(c[mf][nf][2] + bb.x, c[mf][nf][3] + bb.y);
        }
    }
}

// ============ flash attention: 2-stage 128-key KV ring (stage0 overlays Q) ============
#define AKH 0
#define AKL 16384
#define AKV 32768
#define AST 49152
#define ATTN_SMEM (2*AST)

__device__ __forceinline__ void load_kv128(uint32_t stage_base,
    const char* Khb, const char* Klb, const char* Vhb, int key0, int tid)
{
    #pragma unroll
    for (int p = 0; p < 4; ++p) {
        int id = tid + p * 256;
        int row = id >> 3, c = id & 7;
        int cs = c ^ (row & 7);
        size_t go = (size_t)(key0 + row) * (DD * 2) + c * 16;
        uint32_t so = (uint32_t)(row * 128 + cs * 16);
        cp_async16(stage_base + AKH + so, Khb + go);
        cp_async16(stage_base + AKL + so, Klb + go);
        cp_async16(stage_base + AKV + so, Vhb + go);
    }
    CP_COMMIT();
}

__global__ __launch_bounds__(256, 2) void attn_kernel(
    const __nv_bfloat16* __restrict__ Qh, const __nv_bfloat16* __restrict__ Ql,
    const __nv_bfloat16* __restrict__ Kh, const __nv_bfloat16* __restrict__ Kl,
    const __half* __restrict__ Vv,
    __nv_bfloat16* __restrict__ Xhi, __nv_bfloat16* __restrict__ Xlo)
{
    extern __shared__ char sm[];
    const uint32_t sb = smem_u32(sm);
    const int tid = threadIdx.x, lane = tid & 31, w = tid >> 5;
    const int q0 = blockIdx.x * 128;
    const int b = blockIdx.y >> 4, h = blockIdx.y & 15;
    const int g = lane >> 2, qr = lane & 3;
    const int wrow = w * 16;

    const char* Qhb = (const char*)(Qh + (size_t)b * SS * DD + h * 64);
    const char* Qlb = (const char*)(Ql + (size_t)b * SS * DD + h * 64);
    const char* Khb = (const char*)(Kh + (size_t)b * SS * DD + h * 64);
    const char* Klb = (const char*)(Kl + (size_t)b * SS * DD + h * 64);
    const char* Vhb = (const char*)(Vv + (size_t)b * SS * DD + h * 64);

    #pragma unroll
    for (int p = 0; p < 4; ++p) {
        int id = tid + p * 256;
        int row = id >> 3, c = id & 7;
        int cs = c ^ (row & 7);
        size_t go = (size_t)(q0 + row) * (DD * 2) + c * 16;
        uint32_t so = (uint32_t)(row * 128 + cs * 16);
        cp_async16(sb + 0 + so, Qhb + go);
        cp_async16(sb + 16384 + so, Qlb + go);
    }
    CP_COMMIT();

    asm volatile("cp.async.wait_group 0;" ::: "memory");
    __syncthreads();
    const int q_row = wrow + (lane & 15);
    const int kq = q_row & 7;
    const int ca = lane >> 4;
    uint32_t qh[4][4], ql[4][4];
    #pragma unroll
    for (int kc = 0; kc < 4; ++kc) {
        uint32_t ra = sb + (uint32_t)(q_row * 128 + (((kc * 2 + ca) ^ kq) << 4));
        LDM_X4(qh[kc], ra);
        LDM_X4(ql[kc], ra + 16384);
    }
    __syncthreads();
    load_kv128(sb, Khb, Klb, Vhb, 0, tid);

    const int k_rowb = ((lane >> 4) << 3) + (lane & 7);
    const int kk = lane & 7;
    const int cb = (lane >> 3) & 1;
    const int v_row = (((lane >> 3) & 1) << 3) + (lane & 7);
    const int kv_key = lane & 7;
    const int cv = lane >> 4;

    float m0 = -1e30f, m1 = -1e30f, l0 = 0.f, l1 = 0.f;
    float o[8][4];
    #pragma unroll
    for (int j = 0; j < 8; ++j)
        #pragma unroll
        for (int e = 0; e < 4; ++e) o[j][e] = 0.f;

    const int NK = SS / 128;
    for (int kt = 0; kt < NK; ++kt) {
        asm volatile("cp.async.wait_group 0;" ::: "memory");
        __syncthreads();
        if (kt + 1 < NK)
            load_kv128(sb + (uint32_t)(((kt + 1) & 1) * AST),
                       Khb, Klb, Vhb, (kt + 1) * 128, tid);

        const uint32_t STb = sb + (uint32_t)((kt & 1) * AST);

        #pragma unroll
        for (int half = 0; half < 2; ++half) {
            const int rbase = half * 64;

            float s[8][4];
            #pragma unroll
            for (int j = 0; j < 8; ++j)
                #pragma unroll
                for (int e = 0; e < 4; ++e) s[j][e] = 0.f;

            #pragma unroll
            for (int kc = 0; kc < 4; ++kc) {
                const uint32_t kcol = (uint32_t)((((kc * 2 + cb) ^ kk) << 4));
                #pragma unroll
                for (int p = 0; p < 4; ++p) {
                    uint32_t rb = STb + AKH
                        + (uint32_t)((rbase + k_rowb + p * 16) * 128) + kcol;
                    uint32_t kh4[4], kl4[4];
                    LDM_X4(kh4, rb);
                    LDM_X4(kl4, rb + (AKL - AKH));
                    MMA_BF16(s[2*p],   qh[kc], kh4[0], kh4[1]);
                    MMA_BF16(s[2*p],   qh[kc], kl4[0], kl4[1]);
                    MMA_BF16(s[2*p],   ql[kc], kh4[0], kh4[1]);
                    MMA_BF16(s[2*p+1], qh[kc], kh4[2], kh4[3]);
                    MMA_BF16(s[2*p+1], qh[kc], kl4[2], kl4[3]);
                    MMA_BF16(s[2*p+1], ql[kc], kh4[2], kh4[3]);
                }
            }

            float mx0 = -1e30f, mx1 = -1e30f;
            #pragma unroll
            for (int j = 0; j < 8; ++j) {
                mx0 = fmaxf(mx0, fmaxf(s[j][0], s[j][1]));
                mx1 = fmaxf(mx1, fmaxf(s[j][2], s[j][3]));
            }
            mx0 = fmaxf(mx0, __shfl_xor_sync(0xffffffffu, mx0, 1));
            mx0 = fmaxf(mx0, __shfl_xor_sync(0xffffffffu, mx0, 2));
            mx1 = fmaxf(mx1, __shfl_xor_sync(0xffffffffu, mx1, 1));
            mx1 = fmaxf(mx1, __shfl_xor_sync(0xffffffffu, mx1, 2));
            float m0n = fmaxf(m0, mx0), m1n = fmaxf(m1, mx1);
            bool nore = __all_sync(0xffffffffu, (m0n == m0) && (m1n == m1));
            if (!nore) {
                float sc0 = ex2(m0 - m0n), sc1 = ex2(m1 - m1n);
                l0 *= sc0; l1 *= sc1;
                #pragma unroll
                for (int j = 0; j < 8; ++j) {
                    o[j][0] *= sc0; o[j][1] *= sc0;
                    o[j][2] *= sc1; o[j][3] *= sc1;
                }
            }
            m0 = m0n; m1 = m1n;

            const uint32_t vbase = STb + AKV;
            #pragma unroll
            for (int kc = 0; kc < 4; ++kc) {
                const int j0 = 2 * kc, j1 = 2 * kc + 1;
                float e00 = ex2(s[j0][0] - m0n), e01 = ex2(s[j0][1] - m0n);
                float e02 = ex2(s[j0][2] - m1n), e03 = ex2(s[j0][3] - m1n);
                float e10 = ex2(s[j1][0] - m0n), e11 = ex2(s[j1][1] - m0n);
                float e12 = ex2(s[j1][2] - m1n), e13 = ex2(s[j1][3] - m1n);
                l0 += e00 + e01 + e10 + e11;
                l1 += e02 + e03 + e12 + e13;
                uint32_t a0 = f2h2(e00, e01);
                uint32_t a1 = f2h2(e02, e03);
                uint32_t a2 = f2h2(e10, e11);
                uint32_t a3 = f2h2(e12, e13);
                const int mrow = rbase + kc * 16 + v_row;
                #pragma unroll
                for (int nfp = 0; nfp < 4; ++nfp) {
                    const int nf = 2 * nfp;
                    uint32_t addr = vbase + (uint32_t)(mrow * 128
                                     + (((nf + cv) ^ kv_key) << 4));
                    uint32_t r0, r1, r2, r3;
                    asm volatile("ldmatrix.sync.aligned.m8n8.x4.trans.shared.b16 {%0,%1,%2,%3}, [%4];"
                        : "=r"(r0), "=r"(r1), "=r"(r2), "=r"(r3) : "r"(addr));
                    MMA_F16(o[nf],     a0, a1, a2, a3, r0, r1);
                    MMA_F16(o[nf + 1], a0, a1, a2, a3, r2, r3);
                }
            }
        }
    }

    l0 += __shfl_xor_sync(0xffffffffu, l0, 1);
    l0 += __shfl_xor_sync(0xffffffffu, l0, 2);
    l1 += __shfl_xor_sync(0xffffffffu, l1, 1);
    l1 += __shfl_xor_sync(0xffffffffu, l1, 2);

    float inv0 = 1.0f / l0, inv1 = 1.0f / l1;
    size_t r0g = ((size_t)(h * BB + b) * SS + q0 + wrow + g) * 64;
    size_t r1g = r0g + 8 * 64;
    #pragma unroll
    for (int nf = 0; nf < 8; ++nf) {
        int col = nf * 8 + qr * 2;
        float v0 = o[nf][0] * inv0, v1 = o[nf][1] * inv0;
        float v2 = o[nf][2] * inv1, v3 = o[nf][3] * inv1;
        __nv_bfloat16 h0 = __float2bfloat16_rn(v0), h1 = __float2bfloat16_rn(v1);
        __nv_bfloat16 h2 = __float2bfloat16_rn(v2), h3 = __float2bfloat16_rn(v3);
        __nv_bfloat162 H0; H0.x = h0; H0.y = h1;
        __nv_bfloat162 H1; H1.x = h2; H1.y = h3;
        __nv_bfloat162 L0, L1;
        L0.x = __float2bfloat16_rn(v0 - __bfloat162float(h0));
        L0.y = __float2bfloat16_rn(v1 - __bfloat162float(h1));
        L1.x = __float2bfloat16_rn(v2 - __bfloat162float(h2));
        L1.y = __float2bfloat16_rn(v3 - __bfloat162float(h3));
        *(__nv_bfloat162*)&Xhi[r0g + col] = H0;
        *(__nv_bfloat162*)&Xhi[r1g + col] = H1;
        *(__nv_bfloat162*)&Xlo[r0g + col] = L0;
        *(__nv_bfloat162*)&Xlo[r1g + col] = L1;
    }
}

extern "C" void kernel_launch(void* const* d_in, const int* in_sizes, int n_in,
                              void* d_out, int out_size)
{
    const float* q  = (const float*)d_in[0];
    const float* k  = (const float*)d_in[1];
    const float* v  = (const float*)d_in[2];
    const float* wq = (const float*)d_in[3];
    const float* bq = (const float*)d_in[4];
    const float* wk = (const float*)d_in[5];
    const float* bk = (const float*)d_in[6];
    const float* wv = (const float*)d_in[7];
    const float* bv = (const float*)d_in[8];
    const float* wo = (const float*)d_in[9];
    const float* bo = (const float*)d_in[10];
    float* out = (float*)d_out;

    __nv_bfloat16 *Whi, *Wlo, *Ahi, *Alo, *Qhi, *Qlo, *Khi, *Klo, *Xhi, *Xlo;
    __half *Vh;
    cudaGetSymbolAddress((void**)&Whi, g_Whi);
    cudaGetSymbolAddress((void**)&Wlo, g_Wlo);
    cudaGetSymbolAddress((void**)&Ahi, g_Ahi);
    cudaGetSymbolAddress((void**)&Alo, g_Alo);
    cudaGetSymbolAddress((void**)&Qhi, g_Qhi);
    cudaGetSymbolAddress((void**)&Qlo, g_Qlo);
    cudaGetSymbolAddress((void**)&Khi, g_Khi);
    cudaGetSymbolAddress((void**)&Klo, g_Klo);
    cudaGetSymbolAddress((void**)&Xhi, g_Xhi);
    cudaGetSymbolAddress((void**)&Xlo, g_Xlo);
    cudaGetSymbolAddress((void**)&Vh,  g_Vh);

    cudaFuncSetAttribute(qkv_gemm,    cudaFuncAttributeMaxDynamicSharedMemorySize, QKV_SMEM);
    cudaFuncSetAttribute(out_gemm,    cudaFuncAttributeMaxDynamicSharedMemorySize, GEMM_SMEM);
    cudaFuncSetAttribute(attn_kernel, cudaFuncAttributeMaxDynamicSharedMemorySize, ATTN_SMEM);

    dim3 pGrid(MTOT * DD / 4 / 256, 1, 4);
    pre_kernel<<<pGrid, 256>>>(q, k, v, wq, wk, wv, wo, Ahi, Alo, Whi, Wlo);

    dim3 qkvGrid(48, MTOT / 128);   // 1536 CTAs of 128x64
    qkv_gemm<<<qkvGrid, 256, QKV_SMEM>>>(Ahi, Alo, Whi, Wlo, bq, bk, bv,
                                         Qhi, Qlo, Khi, Klo, Vh);

    dim3 aGrid(SS / 128, BB * HH);
    attn_kernel<<<aGrid, 256, ATTN_SMEM>>>(Qhi, Qlo, Khi, Klo, Vh, Xhi, Xlo);

    dim3 oGrid(DD / 128, MTOT / 128);
    out_gemm<<<oGrid, 256, GEMM_SMEM>>>(Xhi, Xlo, Whi + 3*(size_t)DD*DD, Wlo + 3*(size_t)DD*DD,
                                        bo, out);
}

// round 14
// speedup vs baseline: 1.0558x; 1.0558x over previous
#include <cuda_runtime.h>
#include <cuda_bf16.h>
#include <cuda_fp16.h>
#include <cstdint>
#include <math.h>

#define BB 2
#define SS 2048
#define DD 1024
#define HH 16
#define DHH 64
#define MTOT (BB*SS)
#define LOG2E 1.44269504088896f

__device__ __align__(256) __nv_bfloat16 g_Whi[4][DD*DD];   // plane 3 holds Wo as fp16
__device__ __align__(256) __nv_bfloat16 g_Wlo[3][DD*DD];
__device__ __align__(256) __nv_bfloat16 g_Ahi[3][MTOT*DD];
__device__ __align__(256) __nv_bfloat16 g_Alo[3][MTOT*DD];
__device__ __align__(256) __nv_bfloat16 g_Qhi[MTOT*DD];
__device__ __align__(256) __nv_bfloat16 g_Qlo[MTOT*DD];
__device__ __align__(256) __nv_bfloat16 g_Khi[MTOT*DD];
__device__ __align__(256) __nv_bfloat16 g_Klo[MTOT*DD];
__device__ __align__(256) __half        g_Vh [MTOT*DD];
__device__ __align__(256) __half        g_Xh16[MTOT*DD];
__device__ __align__(256) __half        g_Xl16[MTOT*DD];

__device__ __forceinline__ uint32_t smem_u32(const void* p) {
    uint32_t a;
    asm("{ .reg .u64 t; cvta.to.shared.u64 t, %1; cvt.u32.u64 %0, t; }" : "=r"(a) : "l"(p));
    return a;
}
__device__ __forceinline__ void cp_async16(uint32_t dst, const void* src) {
    asm volatile("cp.async.cg.shared.global [%0], [%1], 16;" :: "r"(dst), "l"(src));
}
#define CP_COMMIT() asm volatile("cp.async.commit_group;" ::: "memory")

#define MMA_BF16(c, a, b0, b1) \
    asm volatile("mma.sync.aligned.m16n8k16.row.col.f32.bf16.bf16.f32 " \
        "{%0,%1,%2,%3}, {%4,%5,%6,%7}, {%8,%9}, {%0,%1,%2,%3};" \
        : "+f"((c)[0]), "+f"((c)[1]), "+f"((c)[2]), "+f"((c)[3]) \
        : "r"((a)[0]), "r"((a)[1]), "r"((a)[2]), "r"((a)[3]), "r"(b0), "r"(b1))

#define MMA_F16(c, a0, a1, a2, a3, b0, b1) \
    asm volatile("mma.sync.aligned.m16n8k16.row.col.f32.f16.f16.f32 " \
        "{%0,%1,%2,%3}, {%4,%5,%6,%7}, {%8,%9}, {%0,%1,%2,%3};" \
        : "+f"((c)[0]), "+f"((c)[1]), "+f"((c)[2]), "+f"((c)[3]) \
        : "r"(a0), "r"(a1), "r"(a2), "r"(a3), "r"(b0), "r"(b1))

#define LDM_X4(r, a) \
    asm volatile("ldmatrix.sync.aligned.m8n8.x4.shared.b16 {%0,%1,%2,%3}, [%4];" \
        : "=r"((r)[0]), "=r"((r)[1]), "=r"((r)[2]), "=r"((r)[3]) : "r"(a))

__device__ __forceinline__ uint32_t f2h2(float x, float y) {
    __half2 t = __floats2half2_rn(x, y);
    return *(uint32_t*)&t;
}
__device__ __forceinline__ float ex2(float x) {
    float y;
    asm("ex2.approx.ftz.f32 %0, %1;" : "=f"(y) : "f"(x));
    return y;
}

// ============ fused prologue ============
// z<3: activation split (bf16 hi/lo). z==3: weight transposes; wsel<3 bf16 hi/lo,
// wsel==3 (Wo) single fp16 into the Whi[3] plane.
__global__ __launch_bounds__(256) void pre_kernel(
    const float* __restrict__ a0, const float* __restrict__ a1,
    const float* __restrict__ a2,
    const float* __restrict__ w0, const float* __restrict__ w1,
    const float* __restrict__ w2, const float* __restrict__ w3,
    __nv_bfloat16* __restrict__ Ahi_base, __nv_bfloat16* __restrict__ Alo_base,
    __nv_bfloat16* __restrict__ Whi_base, __nv_bfloat16* __restrict__ Wlo_base)
{
    if (blockIdx.z < 3) {
        int i = blockIdx.x * 256 + threadIdx.x;
        const float* a = (blockIdx.z == 0) ? a0 : (blockIdx.z == 1) ? a1 : a2;
        __nv_bfloat16* hi = Ahi_base + (size_t)blockIdx.z * MTOT * DD;
        __nv_bfloat16* lo = Alo_base + (size_t)blockIdx.z * MTOT * DD;
        float4 v = ((const float4*)a)[i];
        __nv_bfloat16 hx = __float2bfloat16_rn(v.x), hy = __float2bfloat16_rn(v.y);
        __nv_bfloat16 hz = __float2bfloat16_rn(v.z), hw = __float2bfloat16_rn(v.w);
        __nv_bfloat162 h0; h0.x = hx; h0.y = hy;
        __nv_bfloat162 h1; h1.x = hz; h1.y = hw;
        __nv_bfloat162 l0, l1;
        l0.x = __float2bfloat16_rn(v.x - __bfloat162float(hx));
        l0.y = __float2bfloat16_rn(v.y - __bfloat162float(hy));
        l1.x = __float2bfloat16_rn(v.z - __bfloat162float(hz));
        l1.y = __float2bfloat16_rn(v.w - __bfloat162float(hw));
        ((__nv_bfloat162*)hi)[i*2+0] = h0; ((__nv_bfloat162*)hi)[i*2+1] = h1;
        ((__nv_bfloat162*)lo)[i*2+0] = l0; ((__nv_bfloat162*)lo)[i*2+1] = l1;
    } else {
        int wsel = blockIdx.x >> 10;
        int tile = blockIdx.x & 1023;
        int bx = tile & 31, by = tile >> 5;
        const float* in = (wsel == 0) ? w0 : (wsel == 1) ? w1 : (wsel == 2) ? w2 : w3;
        __shared__ float t[32][33];
        int tx = threadIdx.x & 31, ty = threadIdx.x >> 5;
        int x = bx * 32 + tx;
        int y = by * 32 + ty;
        #pragma unroll
        for (int j = 0; j < 32; j += 8)
            t[ty + j][tx] = in[(size_t)(y + j) * DD + x];
        __syncthreads();
        int x2 = by * 32 + tx;
        int y2 = bx * 32 + ty;
        if (wsel == 3) {
            __half* w16 = (__half*)(Whi_base + 3 * (size_t)DD * DD);
            #pragma unroll
            for (int j = 0; j < 32; j += 8)
                w16[(size_t)(y2 + j) * DD + x2] = __float2half_rn(t[tx][ty + j]);
        } else {
            __nv_bfloat16* hi = Whi_base + (size_t)wsel * DD * DD;
            __nv_bfloat16* lo = Wlo_base + (size_t)wsel * DD * DD;
            #pragma unroll
            for (int j = 0; j < 32; j += 8) {
                float w = t[tx][ty + j];
                __nv_bfloat16 h = __float2bfloat16_rn(w);
                hi[(size_t)(y2 + j) * DD + x2] = h;
                lo[(size_t)(y2 + j) * DD + x2] = __float2bfloat16_rn(w - __bfloat162float(h));
            }
        }
    }
}

// ============ split-bf16 QKV GEMM: 128x128, 3-stage, occ 2 ============
#define T_AH    0
#define T_AL    8192
#define T_BH    16384
#define T_BL    24576
#define STAGE   32768
#define GEMM_SMEM (3*STAGE)

__device__ __forceinline__ void load_chunk_g(
    uint32_t sbase, int st,
    const __nv_bfloat16* __restrict__ Ah, const __nv_bfloat16* __restrict__ Al,
    const __nv_bfloat16* __restrict__ Bh, const __nv_bfloat16* __restrict__ Bl,
    int bm, int bn, int k0, int tid)
{
    uint32_t s = sbase + st * STAGE;
    #pragma unroll
    for (int it = 0; it < 2; ++it) {
        int idx = tid + it * 256;
        int row = idx >> 2, q = idx & 3;
        int qs = q ^ ((row >> 1) & 3);
        uint32_t doff = (uint32_t)(row * 64 + qs * 16);
        size_t ga = (size_t)(bm + row) * DD + k0 + q * 8;
        size_t gb = (size_t)(bn + row) * DD + k0 + q * 8;
        cp_async16(s + T_AH + doff, Ah + ga);
        cp_async16(s + T_AL + doff, Al + ga);
        cp_async16(s + T_BH + doff, Bh + gb);
        cp_async16(s + T_BL + doff, Bl + gb);
    }
    CP_COMMIT();
}

__global__ __launch_bounds__(256, 2) void qkv_gemm(
    const __nv_bfloat16* __restrict__ Ahi_all, const __nv_bfloat16* __restrict__ Alo_all,
    const __nv_bfloat16* __restrict__ Whi_all, const __nv_bfloat16* __restrict__ Wlo_all,
    const float* __restrict__ bq, const float* __restrict__ bk, const float* __restrict__ bv,
    __nv_bfloat16* __restrict__ Qhi, __nv_bfloat16* __restrict__ Qlo,
    __nv_bfloat16* __restrict__ Khi, __nv_bfloat16* __restrict__ Klo,
    __half* __restrict__ Vh)
{
    extern __shared__ char smem[];
    const uint32_t sbase = smem_u32(smem);
    const int tid = threadIdx.x, wid = tid >> 5, lane = tid & 31;
    const int warp_m = wid & 1, warp_n = wid >> 1;
    const int proj = blockIdx.x >> 3;
    const int bn = (blockIdx.x & 7) * 128;
    const int bm = blockIdx.y * 128;

    const __nv_bfloat16* Ah = Ahi_all + (size_t)proj * MTOT * DD;
    const __nv_bfloat16* Al = Alo_all + (size_t)proj * MTOT * DD;
    const __nv_bfloat16* Bh = Whi_all + (size_t)proj * DD * DD;
    const __nv_bfloat16* Bl = Wlo_all + (size_t)proj * DD * DD;
    const float* bias = (proj == 0) ? bq : (proj == 1) ? bk : bv;
    const float oscale = (proj == 0) ? LOG2E : 1.0f;

    const int a_row = warp_m * 64 + (lane & 15);
    const int sA = (a_row >> 1) & 3;
    const int b_row = warp_n * 32 + ((lane >> 4) << 3) + (lane & 7);
    const int sB = (b_row >> 1) & 3;
    const int ca = (lane >> 4);
    const int cb = ((lane >> 3) & 1);

    float c[4][4][4];
    #pragma unroll
    for (int i = 0; i < 4; ++i)
        #pragma unroll
        for (int j = 0; j < 4; ++j)
            #pragma unroll
            for (int e = 0; e < 4; ++e) c[i][j][e] = 0.f;

    load_chunk_g(sbase, 0, Ah, Al, Bh, Bl, bm, bn, 0,  tid);
    load_chunk_g(sbase, 1, Ah, Al, Bh, Bl, bm, bn, 32, tid);

    const int NCHUNK = DD / 32;
    for (int i = 0; i < NCHUNK; ++i) {
        const int st = i % 3;
        if (i < NCHUNK - 1) asm volatile("cp.async.wait_group 1;" ::: "memory");
        else                asm volatile("cp.async.wait_group 0;" ::: "memory");
        __syncthreads();
        if (i + 2 < NCHUNK)
            load_chunk_g(sbase, (i + 2) % 3, Ah, Al, Bh, Bl, bm, bn, (i + 2) * 32, tid);

        const uint32_t stb = sbase + st * STAGE;
        #pragma unroll
        for (int ks = 0; ks < 2; ++ks) {
            uint32_t ah[4][4], al[4][4], bh[2][4], bl[2][4];
            const uint32_t ac = (uint32_t)(((ks * 2 + ca) ^ sA) << 4);
            const uint32_t bc = (uint32_t)(((ks * 2 + cb) ^ sB) << 4);
            #pragma unroll
            for (int mf = 0; mf < 4; ++mf) {
                uint32_t ra = stb + T_AH + (uint32_t)((a_row + mf * 16) * 64) + ac;
                LDM_X4(ah[mf], ra);
                LDM_X4(al[mf], ra + (T_AL - T_AH));
            }
            #pragma unroll
            for (int p = 0; p < 2; ++p) {
                uint32_t rb = stb + T_BH + (uint32_t)((b_row + p * 16) * 64) + bc;
                LDM_X4(bh[p], rb);
                LDM_X4(bl[p], rb + (T_BL - T_BH));
            }
            #pragma unroll
            for (int mf = 0; mf < 4; ++mf)
                #pragma unroll
                for (int nf = 0; nf < 4; ++nf) {
                    const int p = nf >> 1, hh = (nf & 1) * 2;
                    MMA_BF16(c[mf][nf], ah[mf], bh[p][hh], bh[p][hh+1]);
                    MMA_BF16(c[mf][nf], ah[mf], bl[p][hh], bl[p][hh+1]);
                    MMA_BF16(c[mf][nf], al[mf], bh[p][hh], bh[p][hh+1]);
                }
        }
    }

    __nv_bfloat16* Oh = (proj == 0) ? Qhi : Khi;
    __nv_bfloat16* Ol = (proj == 0) ? Qlo : Klo;

    #pragma unroll
    for (int mf = 0; mf < 4; ++mf) {
        int m0 = bm + warp_m * 64 + mf * 16 + (lane >> 2);
        #pragma unroll
        for (int nf = 0; nf < 4; ++nf) {
            int n = bn + warp_n * 32 + nf * 8 + (lane & 3) * 2;
            float2 bb = *(const float2*)&bias[n];
            float v0 = (c[mf][nf][0] + bb.x) * oscale, v1 = (c[mf][nf][1] + bb.y) * oscale;
            float v2 = (c[mf][nf][2] + bb.x) * oscale, v3 = (c[mf][nf][3] + bb.y) * oscale;
            size_t i0 = (size_t)m0 * DD + n, i1 = (size_t)(m0 + 8) * DD + n;
            if (proj == 2) {
                *(__half2*)&Vh[i0] = __floats2half2_rn(v0, v1);
                *(__half2*)&Vh[i1] = __floats2half2_rn(v2, v3);
            } else {
                __nv_bfloat16 h0 = __float2bfloat16_rn(v0), h1 = __float2bfloat16_rn(v1);
                __nv_bfloat16 h2 = __float2bfloat16_rn(v2), h3 = __float2bfloat16_rn(v3);
                __nv_bfloat162 H0; H0.x = h0; H0.y = h1;
                __nv_bfloat162 H1; H1.x = h2; H1.y = h3;
                __nv_bfloat162 L0, L1;
                L0.x = __float2bfloat16_rn(v0 - __bfloat162float(h0));
                L0.y = __float2bfloat16_rn(v1 - __bfloat162float(h1));
                L1.x = __float2bfloat16_rn(v2 - __bfloat162float(h2));
                L1.y = __float2bfloat16_rn(v3 - __bfloat162float(h3));
                *(__nv_bfloat162*)&Oh[i0] = H0; *(__nv_bfloat162*)&Oh[i1] = H1;
                *(__nv_bfloat162*)&Ol[i0] = L0; *(__nv_bfloat162*)&Ol[i1] = L1;
            }
        }
    }
}

// ============ fp16 2-MMA out GEMM: X(fp16 hi/lo) @ Wo(fp16) + bias ============
#define O_AH 0
#define O_AL 8192
#define O_B  16384
#define O_STAGE 24576
#define OUT_SMEM (3*O_STAGE)   // 73728

__device__ __forceinline__ void load_chunk_o(
    uint32_t sbase, int st,
    const __half* __restrict__ Xh, const __half* __restrict__ Xl,
    const __half* __restrict__ W16,
    int bm, int bn, int k0, int tid)
{
    uint32_t s = sbase + st * O_STAGE;
    #pragma unroll
    for (int it = 0; it < 2; ++it) {
        int idx = tid + it * 256;
        int row = idx >> 2, q = idx & 3;
        int qs = q ^ ((row >> 1) & 3);
        uint32_t doff = (uint32_t)(row * 64 + qs * 16);
        size_t ga = (size_t)(bm + row) * DD + k0 + q * 8;
        size_t gb = (size_t)(bn + row) * DD + k0 + q * 8;
        cp_async16(s + O_AH + doff, Xh + ga);
        cp_async16(s + O_AL + doff, Xl + ga);
        cp_async16(s + O_B  + doff, W16 + gb);
    }
    CP_COMMIT();
}

__global__ __launch_bounds__(256, 2) void out_gemm(
    const __half* __restrict__ Xh, const __half* __restrict__ Xl,
    const __half* __restrict__ W16,
    const float* __restrict__ bias, float* __restrict__ C)
{
    extern __shared__ char smem[];
    const uint32_t sbase = smem_u32(smem);
    const int tid = threadIdx.x, wid = tid >> 5, lane = tid & 31;
    const int warp_m = wid & 1, warp_n = wid >> 1;
    const int bm = blockIdx.y * 128, bn = blockIdx.x * 128;

    const int a_row = warp_m * 64 + (lane & 15);
    const int sA = (a_row >> 1) & 3;
    const int b_row = warp_n * 32 + ((lane >> 4) << 3) + (lane & 7);
    const int sB = (b_row >> 1) & 3;
    const int ca = (lane >> 4);
    const int cb = ((lane >> 3) & 1);

    float c[4][4][4];
    #pragma unroll
    for (int i = 0; i < 4; ++i)
        #pragma unroll
        for (int j = 0; j < 4; ++j)
            #pragma unroll
            for (int e = 0; e < 4; ++e) c[i][j][e] = 0.f;

    load_chunk_o(sbase, 0, Xh, Xl, W16, bm, bn, 0,  tid);
    load_chunk_o(sbase, 1, Xh, Xl, W16, bm, bn, 32, tid);

    const int NCHUNK = DD / 32;
    for (int i = 0; i < NCHUNK; ++i) {
        const int st = i % 3;
        if (i < NCHUNK - 1) asm volatile("cp.async.wait_group 1;" ::: "memory");
        else                asm volatile("cp.async.wait_group 0;" ::: "memory");
        __syncthreads();
        if (i + 2 < NCHUNK)
            load_chunk_o(sbase, (i + 2) % 3, Xh, Xl, W16, bm, bn, (i + 2) * 32, tid);

        const uint32_t stb = sbase + st * O_STAGE;
        #pragma unroll
        for (int ks = 0; ks < 2; ++ks) {
            uint32_t ah[4][4], al[4][4], bh[2][4];
            const uint32_t ac = (uint32_t)(((ks * 2 + ca) ^ sA) << 4);
            const uint32_t bc = (uint32_t)(((ks * 2 + cb) ^ sB) << 4);
            #pragma unroll
            for (int mf = 0; mf < 4; ++mf) {
                uint32_t ra = stb + O_AH + (uint32_t)((a_row + mf * 16) * 64) + ac;
                LDM_X4(ah[mf], ra);
                LDM_X4(al[mf], ra + (O_AL - O_AH));
            }
            #pragma unroll
            for (int p = 0; p < 2; ++p) {
                uint32_t rb = stb + O_B + (uint32_t)((b_row + p * 16) * 64) + bc;
                LDM_X4(bh[p], rb);
            }
            #pragma unroll
            for (int mf = 0; mf < 4; ++mf)
                #pragma unroll
                for (int nf = 0; nf < 4; ++nf) {
                    const int p = nf >> 1, hh = (nf & 1) * 2;
                    MMA_F16(c[mf][nf], ah[mf][0], ah[mf][1], ah[mf][2], ah[mf][3],
                            bh[p][hh], bh[p][hh+1]);
                    MMA_F16(c[mf][nf], al[mf][0], al[mf][1], al[mf][2], al[mf][3],
                            bh[p][hh], bh[p][hh+1]);
                }
        }
    }

    #pragma unroll
    for (int mf = 0; mf < 4; ++mf) {
        int m0 = bm + warp_m * 64 + mf * 16 + (lane >> 2);
        #pragma unroll
        for (int nf = 0; nf < 4; ++nf) {
            int n = bn + warp_n * 32 + nf * 8 + (lane & 3) * 2;
            float2 bb = *(const float2*)&bias[n];
            *(float2*)&C[(size_t)m0 * DD + n] =
                make_float2(c[mf][nf][0] + bb.x, c[mf][nf][1] + bb.y);
            *(float2*)&C[(size_t)(m0 + 8) * DD + n] =
                make_float2(c[mf][nf][2] + bb.x, c[mf][nf][3] + bb.y);
        }
    }
}

// ============ flash attention: 2-stage 128-key KV ring (stage0 overlays Q) ============
#define AKH 0
#define AKL 16384
#define AKV 32768
#define AST 49152
#define ATTN_SMEM (2*AST)

__device__ __forceinline__ void load_kv128(uint32_t stage_base,
    const char* Khb, const char* Klb, const char* Vhb, int key0, int tid)
{
    #pragma unroll
    for (int p = 0; p < 4; ++p) {
        int id = tid + p * 256;
        int row = id >> 3, c = id & 7;
        int cs = c ^ (row & 7);
        size_t go = (size_t)(key0 + row) * (DD * 2) + c * 16;
        uint32_t so = (uint32_t)(row * 128 + cs * 16);
        cp_async16(stage_base + AKH + so, Khb + go);
        cp_async16(stage_base + AKL + so, Klb + go);
        cp_async16(stage_base + AKV + so, Vhb + go);
    }
    CP_COMMIT();
}

__global__ __launch_bounds__(256, 2) void attn_kernel(
    const __nv_bfloat16* __restrict__ Qh, const __nv_bfloat16* __restrict__ Ql,
    const __nv_bfloat16* __restrict__ Kh, const __nv_bfloat16* __restrict__ Kl,
    const __half* __restrict__ Vv,
    __half* __restrict__ Xh, __half* __restrict__ Xl)
{
    extern __shared__ char sm[];
    const uint32_t sb = smem_u32(sm);
    const int tid = threadIdx.x, lane = tid & 31, w = tid >> 5;
    const int q0 = blockIdx.x * 128;
    const int b = blockIdx.y >> 4, h = blockIdx.y & 15;
    const int g = lane >> 2, qr = lane & 3;
    const int wrow = w * 16;

    const char* Qhb = (const char*)(Qh + (size_t)b * SS * DD + h * 64);
    const char* Qlb = (const char*)(Ql + (size_t)b * SS * DD + h * 64);
    const char* Khb = (const char*)(Kh + (size_t)b * SS * DD + h * 64);
    const char* Klb = (const char*)(Kl + (size_t)b * SS * DD + h * 64);
    const char* Vhb = (const char*)(Vv + (size_t)b * SS * DD + h * 64);

    #pragma unroll
    for (int p = 0; p < 4; ++p) {
        int id = tid + p * 256;
        int row = id >> 3, c = id & 7;
        int cs = c ^ (row & 7);
        size_t go = (size_t)(q0 + row) * (DD * 2) + c * 16;
        uint32_t so = (uint32_t)(row * 128 + cs * 16);
        cp_async16(sb + 0 + so, Qhb + go);
        cp_async16(sb + 16384 + so, Qlb + go);
    }
    CP_COMMIT();

    asm volatile("cp.async.wait_group 0;" ::: "memory");
    __syncthreads();
    const int q_row = wrow + (lane & 15);
    const int kq = q_row & 7;
    const int ca = lane >> 4;
    uint32_t qh[4][4], ql[4][4];
    #pragma unroll
    for (int kc = 0; kc < 4; ++kc) {
        uint32_t ra = sb + (uint32_t)(q_row * 128 + (((kc * 2 + ca) ^ kq) << 4));
        LDM_X4(qh[kc], ra);
        LDM_X4(ql[kc], ra + 16384);
    }
    __syncthreads();
    load_kv128(sb, Khb, Klb, Vhb, 0, tid);

    const int k_rowb = ((lane >> 4) << 3) + (lane & 7);
    const int kk = lane & 7;
    const int cb = (lane >> 3) & 1;
    const int v_row = (((lane >> 3) & 1) << 3) + (lane & 7);
    const int kv_key = lane & 7;
    const int cv = lane >> 4;

    float m0 = -1e30f, m1 = -1e30f, l0 = 0.f, l1 = 0.f;
    float o[8][4];
    #pragma unroll
    for (int j = 0; j < 8; ++j)
        #pragma unroll
        for (int e = 0; e < 4; ++e) o[j][e] = 0.f;

    const int NK = SS / 128;
    for (int kt = 0; kt < NK; ++kt) {
        asm volatile("cp.async.wait_group 0;" ::: "memory");
        __syncthreads();
        if (kt + 1 < NK)
            load_kv128(sb + (uint32_t)(((kt + 1) & 1) * AST),
                       Khb, Klb, Vhb, (kt + 1) * 128, tid);

        const uint32_t STb = sb + (uint32_t)((kt & 1) * AST);

        #pragma unroll
        for (int half = 0; half < 2; ++half) {
            const int rbase = half * 64;

            float s[8][4];
            #pragma unroll
            for (int j = 0; j < 8; ++j)
                #pragma unroll
                for (int e = 0; e < 4; ++e) s[j][e] = 0.f;

            #pragma unroll
            for (int kc = 0; kc < 4; ++kc) {
                const uint32_t kcol = (uint32_t)((((kc * 2 + cb) ^ kk) << 4));
                #pragma unroll
                for (int p = 0; p < 4; ++p) {
                    uint32_t rb = STb + AKH
                        + (uint32_t)((rbase + k_rowb + p * 16) * 128) + kcol;
                    uint32_t kh4[4], kl4[4];
                    LDM_X4(kh4, rb);
                    LDM_X4(kl4, rb + (AKL - AKH));
                    MMA_BF16(s[2*p],   qh[kc], kh4[0], kh4[1]);
                    MMA_BF16(s[2*p],   qh[kc], kl4[0], kl4[1]);
                    MMA_BF16(s[2*p],   ql[kc], kh4[0], kh4[1]);
                    MMA_BF16(s[2*p+1], qh[kc], kh4[2], kh4[3]);
                    MMA_BF16(s[2*p+1], qh[kc], kl4[2], kl4[3]);
                    MMA_BF16(s[2*p+1], ql[kc], kh4[2], kh4[3]);
                }
            }

            float mx0 = -1e30f, mx1 = -1e30f;
            #pragma unroll
            for (int j = 0; j < 8; ++j) {
                mx0 = fmaxf(mx0, fmaxf(s[j][0], s[j][1]));
                mx1 = fmaxf(mx1, fmaxf(s[j][2], s[j][3]));
            }
            mx0 = fmaxf(mx0, __shfl_xor_sync(0xffffffffu, mx0, 1));
            mx0 = fmaxf(mx0, __shfl_xor_sync(0xffffffffu, mx0, 2));
            mx1 = fmaxf(mx1, __shfl_xor_sync(0xffffffffu, mx1, 1));
            mx1 = fmaxf(mx1, __shfl_xor_sync(0xffffffffu, mx1, 2));
            float m0n = fmaxf(m0, mx0), m1n = fmaxf(m1, mx1);
            bool nore = __all_sync(0xffffffffu, (m0n == m0) && (m1n == m1));
            if (!nore) {
                float sc0 = ex2(m0 - m0n), sc1 = ex2(m1 - m1n);
                l0 *= sc0; l1 *= sc1;
                #pragma unroll
                for (int j = 0; j < 8; ++j) {
                    o[j][0] *= sc0; o[j][1] *= sc0;
                    o[j][2] *= sc1; o[j][3] *= sc1;
                }
            }
            m0 = m0n; m1 = m1n;

            const uint32_t vbase = STb + AKV;
            #pragma unroll
            for (int kc = 0; kc < 4; ++kc) {
                const int j0 = 2 * kc, j1 = 2 * kc + 1;
                float e00 = ex2(s[j0][0] - m0n), e01 = ex2(s[j0][1] - m0n);
                float e02 = ex2(s[j0][2] - m1n), e03 = ex2(s[j0][3] - m1n);
                float e10 = ex2(s[j1][0] - m0n), e11 = ex2(s[j1][1] - m0n);
                float e12 = ex2(s[j1][2] - m1n), e13 = ex2(s[j1][3] - m1n);
                l0 += e00 + e01 + e10 + e11;
                l1 += e02 + e03 + e12 + e13;
                uint32_t a0 = f2h2(e00, e01);
                uint32_t a1 = f2h2(e02, e03);
                uint32_t a2 = f2h2(e10, e11);
                uint32_t a3 = f2h2(e12, e13);
                const int mrow = rbase + kc * 16 + v_row;
                #pragma unroll
                for (int nfp = 0; nfp < 4; ++nfp) {
                    const int nf = 2 * nfp;
                    uint32_t addr = vbase + (uint32_t)(mrow * 128
                                     + (((nf + cv) ^ kv_key) << 4));
                    uint32_t r0, r1, r2, r3;
                    asm volatile("ldmatrix.sync.aligned.m8n8.x4.trans.shared.b16 {%0,%1,%2,%3}, [%4];"
                        : "=r"(r0), "=r"(r1), "=r"(r2), "=r"(r3) : "r"(addr));
                    MMA_F16(o[nf],     a0, a1, a2, a3, r0, r1);
                    MMA_F16(o[nf + 1], a0, a1, a2, a3, r2, r3);
                }
            }
        }
    }

    l0 += __shfl_xor_sync(0xffffffffu, l0, 1);
    l0 += __shfl_xor_sync(0xffffffffu, l0, 2);
    l1 += __shfl_xor_sync(0xffffffffu, l1, 1);
    l1 += __shfl_xor_sync(0xffffffffu, l1, 2);

    float inv0 = 1.0f / l0, inv1 = 1.0f / l1;
    size_t r0g = ((size_t)(h * BB + b) * SS + q0 + wrow + g) * 64;
    size_t r1g = r0g + 8 * 64;
    #pragma unroll
    for (int nf = 0; nf < 8; ++nf) {
        int col = nf * 8 + qr * 2;
        float v0 = o[nf][0] * inv0, v1 = o[nf][1] * inv0;
        float v2 = o[nf][2] * inv1, v3 = o[nf][3] * inv1;
        __half h0 = __float2half_rn(v0), h1 = __float2half_rn(v1);
        __half h2 = __float2half_rn(v2), h3 = __float2half_rn(v3);
        __half2 H0; H0.x = h0; H0.y = h1;
        __half2 H1; H1.x = h2; H1.y = h3;
        __half2 L0, L1;
        L0.x = __float2half_rn(v0 - __half2float(h0));
        L0.y = __float2half_rn(v1 - __half2float(h1));
        L1.x = __float2half_rn(v2 - __half2float(h2));
        L1.y = __float2half_rn(v3 - __half2float(h3));
        *(__half2*)&Xh[r0g + col] = H0;
        *(__half2*)&Xh[r1g + col] = H1;
        *(__half2*)&Xl[r0g + col] = L0;
        *(__half2*)&Xl[r1g + col] = L1;
    }
}

extern "C" void kernel_launch(void* const* d_in, const int* in_sizes, int n_in,
                              void* d_out, int out_size)
{
    const float* q  = (const float*)d_in[0];
    const float* k  = (const float*)d_in[1];
    const float* v  = (const float*)d_in[2];
    const float* wq = (const float*)d_in[3];
    const float* bq = (const float*)d_in[4];
    const float* wk = (const float*)d_in[5];
    const float* bk = (const float*)d_in[6];
    const float* wv = (const float*)d_in[7];
    const float* bv = (const float*)d_in[8];
    const float* wo = (const float*)d_in[9];
    const float* bo = (const float*)d_in[10];
    float* out = (float*)d_out;

    __nv_bfloat16 *Whi, *Wlo, *Ahi, *Alo, *Qhi, *Qlo, *Khi, *Klo;
    __half *Vh, *Xh, *Xl;
    cudaGetSymbolAddress((void**)&Whi, g_Whi);
    cudaGetSymbolAddress((void**)&Wlo, g_Wlo);
    cudaGetSymbolAddress((void**)&Ahi, g_Ahi);
    cudaGetSymbolAddress((void**)&Alo, g_Alo);
    cudaGetSymbolAddress((void**)&Qhi, g_Qhi);
    cudaGetSymbolAddress((void**)&Qlo, g_Qlo);
    cudaGetSymbolAddress((void**)&Khi, g_Khi);
    cudaGetSymbolAddress((void**)&Klo, g_Klo);
    cudaGetSymbolAddress((void**)&Vh,  g_Vh);
    cudaGetSymbolAddress((void**)&Xh,  g_Xh16);
    cudaGetSymbolAddress((void**)&Xl,  g_Xl16);

    cudaFuncSetAttribute(qkv_gemm,    cudaFuncAttributeMaxDynamicSharedMemorySize, GEMM_SMEM);
    cudaFuncSetAttribute(out_gemm,    cudaFuncAttributeMaxDynamicSharedMemorySize, OUT_SMEM);
    cudaFuncSetAttribute(attn_kernel, cudaFuncAttributeMaxDynamicSharedMemorySize, ATTN_SMEM);

    dim3 pGrid(MTOT * DD / 4 / 256, 1, 4);
    pre_kernel<<<pGrid, 256>>>(q, k, v, wq, wk, wv, wo, Ahi, Alo, Whi, Wlo);

    dim3 qkvGrid(24, MTOT / 128);
    qkv_gemm<<<qkvGrid, 256, GEMM_SMEM>>>(Ahi, Alo, Whi, Wlo, bq, bk, bv,
                                          Qhi, Qlo, Khi, Klo, Vh);

    dim3 aGrid(SS / 128, BB * HH);
    attn_kernel<<<aGrid, 256, ATTN_SMEM>>>(Qhi, Qlo, Khi, Klo, Vh, Xh, Xl);

    dim3 oGrid(DD / 128, MTOT / 128);
    out_gemm<<<oGrid, 256, OUT_SMEM>>>(Xh, Xl, (const __half*)(Whi + 3*(size_t)DD*DD),
                                       bo, out);
}

// round 15
// speedup vs baseline: 1.0837x; 1.0264x over previous
#include <cuda_runtime.h>
#include <cuda_bf16.h>
#include <cuda_fp16.h>
#include <cstdint>
#include <math.h>

#define BB 2
#define SS 2048
#define DD 1024
#define HH 16
#define DHH 64
#define MTOT (BB*SS)
#define LOG2E 1.44269504088896f

// Whi plane 2 = Wv as fp16, plane 3 = Wo as fp16. Ahi/Alo plane 2 = v act as fp16.
__device__ __align__(256) __nv_bfloat16 g_Whi[4][DD*DD];
__device__ __align__(256) __nv_bfloat16 g_Wlo[2][DD*DD];
__device__ __align__(256) __nv_bfloat16 g_Ahi[3][MTOT*DD];
__device__ __align__(256) __nv_bfloat16 g_Alo[3][MTOT*DD];
__device__ __align__(256) __nv_bfloat16 g_Qhi[MTOT*DD];
__device__ __align__(256) __nv_bfloat16 g_Qlo[MTOT*DD];
__device__ __align__(256) __nv_bfloat16 g_Khi[MTOT*DD];
__device__ __align__(256) __nv_bfloat16 g_Klo[MTOT*DD];
__device__ __align__(256) __half        g_Vh [MTOT*DD];
__device__ __align__(256) __half        g_Xh16[MTOT*DD];
__device__ __align__(256) __half        g_Xl16[MTOT*DD];

__device__ __forceinline__ uint32_t smem_u32(const void* p) {
    uint32_t a;
    asm("{ .reg .u64 t; cvta.to.shared.u64 t, %1; cvt.u32.u64 %0, t; }" : "=r"(a) : "l"(p));
    return a;
}
__device__ __forceinline__ void cp_async16(uint32_t dst, const void* src) {
    asm volatile("cp.async.cg.shared.global [%0], [%1], 16;" :: "r"(dst), "l"(src));
}
#define CP_COMMIT() asm volatile("cp.async.commit_group;" ::: "memory")

#define MMA_BF16(c, a, b0, b1) \
    asm volatile("mma.sync.aligned.m16n8k16.row.col.f32.bf16.bf16.f32 " \
        "{%0,%1,%2,%3}, {%4,%5,%6,%7}, {%8,%9}, {%0,%1,%2,%3};" \
        : "+f"((c)[0]), "+f"((c)[1]), "+f"((c)[2]), "+f"((c)[3]) \
        : "r"((a)[0]), "r"((a)[1]), "r"((a)[2]), "r"((a)[3]), "r"(b0), "r"(b1))

#define MMA_F16(c, a0, a1, a2, a3, b0, b1) \
    asm volatile("mma.sync.aligned.m16n8k16.row.col.f32.f16.f16.f32 " \
        "{%0,%1,%2,%3}, {%4,%5,%6,%7}, {%8,%9}, {%0,%1,%2,%3};" \
        : "+f"((c)[0]), "+f"((c)[1]), "+f"((c)[2]), "+f"((c)[3]) \
        : "r"(a0), "r"(a1), "r"(a2), "r"(a3), "r"(b0), "r"(b1))

#define LDM_X4(r, a) \
    asm volatile("ldmatrix.sync.aligned.m8n8.x4.shared.b16 {%0,%1,%2,%3}, [%4];" \
        : "=r"((r)[0]), "=r"((r)[1]), "=r"((r)[2]), "=r"((r)[3]) : "r"(a))

__device__ __forceinline__ uint32_t f2h2(float x, float y) {
    __half2 t = __floats2half2_rn(x, y);
    return *(uint32_t*)&t;
}
__device__ __forceinline__ float ex2(float x) {
    float y;
    asm("ex2.approx.ftz.f32 %0, %1;" : "=f"(y) : "f"(x));
    return y;
}

// ============ fused prologue ============
// z==0,1: bf16 hi/lo split of q,k. z==2: fp16 hi/lo split of v.
// z==3: weight transposes; wsel 0,1 bf16 hi/lo; wsel 2 (Wv) and 3 (Wo) single fp16.
__global__ __launch_bounds__(256) void pre_kernel(
    const float* __restrict__ a0, const float* __restrict__ a1,
    const float* __restrict__ a2,
    const float* __restrict__ w0, const float* __restrict__ w1,
    const float* __restrict__ w2, const float* __restrict__ w3,
    __nv_bfloat16* __restrict__ Ahi_base, __nv_bfloat16* __restrict__ Alo_base,
    __nv_bfloat16* __restrict__ Whi_base, __nv_bfloat16* __restrict__ Wlo_base)
{
    if (blockIdx.z < 3) {
        int i = blockIdx.x * 256 + threadIdx.x;
        const float* a = (blockIdx.z == 0) ? a0 : (blockIdx.z == 1) ? a1 : a2;
        float4 v = ((const float4*)a)[i];
        if (blockIdx.z == 2) {
            __half* hi = (__half*)(Ahi_base + 2 * (size_t)MTOT * DD);
            __half* lo = (__half*)(Alo_base + 2 * (size_t)MTOT * DD);
            __half hx = __float2half_rn(v.x), hy = __float2half_rn(v.y);
            __half hz = __float2half_rn(v.z), hw = __float2half_rn(v.w);
            __half2 h0; h0.x = hx; h0.y = hy;
            __half2 h1; h1.x = hz; h1.y = hw;
            __half2 l0, l1;
            l0.x = __float2half_rn(v.x - __half2float(hx));
            l0.y = __float2half_rn(v.y - __half2float(hy));
            l1.x = __float2half_rn(v.z - __half2float(hz));
            l1.y = __float2half_rn(v.w - __half2float(hw));
            ((__half2*)hi)[i*2+0] = h0; ((__half2*)hi)[i*2+1] = h1;
            ((__half2*)lo)[i*2+0] = l0; ((__half2*)lo)[i*2+1] = l1;
        } else {
            __nv_bfloat16* hi = Ahi_base + (size_t)blockIdx.z * MTOT * DD;
            __nv_bfloat16* lo = Alo_base + (size_t)blockIdx.z * MTOT * DD;
            __nv_bfloat16 hx = __float2bfloat16_rn(v.x), hy = __float2bfloat16_rn(v.y);
            __nv_bfloat16 hz = __float2bfloat16_rn(v.z), hw = __float2bfloat16_rn(v.w);
            __nv_bfloat162 h0; h0.x = hx; h0.y = hy;
            __nv_bfloat162 h1; h1.x = hz; h1.y = hw;
            __nv_bfloat162 l0, l1;
            l0.x = __float2bfloat16_rn(v.x - __bfloat162float(hx));
            l0.y = __float2bfloat16_rn(v.y - __bfloat162float(hy));
            l1.x = __float2bfloat16_rn(v.z - __bfloat162float(hz));
            l1.y = __float2bfloat16_rn(v.w - __bfloat162float(hw));
            ((__nv_bfloat162*)hi)[i*2+0] = h0; ((__nv_bfloat162*)hi)[i*2+1] = h1;
            ((__nv_bfloat162*)lo)[i*2+0] = l0; ((__nv_bfloat162*)lo)[i*2+1] = l1;
        }
    } else {
        int wsel = blockIdx.x >> 10;
        int tile = blockIdx.x & 1023;
        int bx = tile & 31, by = tile >> 5;
        const float* in = (wsel == 0) ? w0 : (wsel == 1) ? w1 : (wsel == 2) ? w2 : w3;
        __shared__ float t[32][33];
        int tx = threadIdx.x & 31, ty = threadIdx.x >> 5;
        int x = bx * 32 + tx;
        int y = by * 32 + ty;
        #pragma unroll
        for (int j = 0; j < 32; j += 8)
            t[ty + j][tx] = in[(size_t)(y + j) * DD + x];
        __syncthreads();
        int x2 = by * 32 + tx;
        int y2 = bx * 32 + ty;
        if (wsel >= 2) {
            __half* w16 = (__half*)(Whi_base + (size_t)wsel * DD * DD);
            #pragma unroll
            for (int j = 0; j < 32; j += 8)
                w16[(size_t)(y2 + j) * DD + x2] = __float2half_rn(t[tx][ty + j]);
        } else {
            __nv_bfloat16* hi = Whi_base + (size_t)wsel * DD * DD;
            __nv_bfloat16* lo = Wlo_base + (size_t)wsel * DD * DD;
            #pragma unroll
            for (int j = 0; j < 32; j += 8) {
                float w = t[tx][ty + j];
                __nv_bfloat16 h = __float2bfloat16_rn(w);
                hi[(size_t)(y2 + j) * DD + x2] = h;
                lo[(size_t)(y2 + j) * DD + x2] = __float2bfloat16_rn(w - __bfloat162float(h));
            }
        }
    }
}

// ============ fused QKV GEMM: 128x128, 3-stage, occ 2 ============
// proj 0,1: bf16-split A x bf16-split W (3 MMAs).  proj 2: fp16-split A x fp16 W (2 MMAs).
#define T_AH    0
#define T_AL    8192
#define T_BH    16384
#define T_BL    24576
#define STAGE   32768
#define GEMM_SMEM (3*STAGE)

__device__ __forceinline__ void load_chunk_g(
    uint32_t sbase, int st,
    const __nv_bfloat16* __restrict__ Ah, const __nv_bfloat16* __restrict__ Al,
    const __nv_bfloat16* __restrict__ Bh, const __nv_bfloat16* __restrict__ Bl,
    int bm, int bn, int k0, int tid, bool loadBl)
{
    uint32_t s = sbase + st * STAGE;
    #pragma unroll
    for (int it = 0; it < 2; ++it) {
        int idx = tid + it * 256;
        int row = idx >> 2, q = idx & 3;
        int qs = q ^ ((row >> 1) & 3);
        uint32_t doff = (uint32_t)(row * 64 + qs * 16);
        size_t ga = (size_t)(bm + row) * DD + k0 + q * 8;
        size_t gb = (size_t)(bn + row) * DD + k0 + q * 8;
        cp_async16(s + T_AH + doff, Ah + ga);
        cp_async16(s + T_AL + doff, Al + ga);
        cp_async16(s + T_BH + doff, Bh + gb);
        if (loadBl) cp_async16(s + T_BL + doff, Bl + gb);
    }
    CP_COMMIT();
}

__global__ __launch_bounds__(256, 2) void qkv_gemm(
    const __nv_bfloat16* __restrict__ Ahi_all, const __nv_bfloat16* __restrict__ Alo_all,
    const __nv_bfloat16* __restrict__ Whi_all, const __nv_bfloat16* __restrict__ Wlo_all,
    const float* __restrict__ bq, const float* __restrict__ bk, const float* __restrict__ bv,
    __nv_bfloat16* __restrict__ Qhi, __nv_bfloat16* __restrict__ Qlo,
    __nv_bfloat16* __restrict__ Khi, __nv_bfloat16* __restrict__ Klo,
    __half* __restrict__ Vh)
{
    extern __shared__ char smem[];
    const uint32_t sbase = smem_u32(smem);
    const int tid = threadIdx.x, wid = tid >> 5, lane = tid & 31;
    const int warp_m = wid & 1, warp_n = wid >> 1;
    const int proj = blockIdx.x >> 3;
    const int bn = (blockIdx.x & 7) * 128;
    const int bm = blockIdx.y * 128;
    const bool isV = (proj == 2);

    const __nv_bfloat16* Ah = Ahi_all + (size_t)proj * MTOT * DD;
    const __nv_bfloat16* Al = Alo_all + (size_t)proj * MTOT * DD;
    const __nv_bfloat16* Bh = Whi_all + (size_t)proj * DD * DD;
    const __nv_bfloat16* Bl = Wlo_all + (size_t)proj * DD * DD;   // unused for proj 2
    const float* bias = (proj == 0) ? bq : (proj == 1) ? bk : bv;
    const float oscale = (proj == 0) ? LOG2E : 1.0f;

    const int a_row = warp_m * 64 + (lane & 15);
    const int sA = (a_row >> 1) & 3;
    const int b_row = warp_n * 32 + ((lane >> 4) << 3) + (lane & 7);
    const int sB = (b_row >> 1) & 3;
    const int ca = (lane >> 4);
    const int cb = ((lane >> 3) & 1);

    float c[4][4][4];
    #pragma unroll
    for (int i = 0; i < 4; ++i)
        #pragma unroll
        for (int j = 0; j < 4; ++j)
            #pragma unroll
            for (int e = 0; e < 4; ++e) c[i][j][e] = 0.f;

    load_chunk_g(sbase, 0, Ah, Al, Bh, Bl, bm, bn, 0,  tid, !isV);
    load_chunk_g(sbase, 1, Ah, Al, Bh, Bl, bm, bn, 32, tid, !isV);

    const int NCHUNK = DD / 32;
    for (int i = 0; i < NCHUNK; ++i) {
        const int st = i % 3;
        if (i < NCHUNK - 1) asm volatile("cp.async.wait_group 1;" ::: "memory");
        else                asm volatile("cp.async.wait_group 0;" ::: "memory");
        __syncthreads();
        if (i + 2 < NCHUNK)
            load_chunk_g(sbase, (i + 2) % 3, Ah, Al, Bh, Bl, bm, bn, (i + 2) * 32, tid, !isV);

        const uint32_t stb = sbase + st * STAGE;
        #pragma unroll
        for (int ks = 0; ks < 2; ++ks) {
            uint32_t ah[4][4], al[4][4], bh[2][4], bl[2][4];
            const uint32_t ac = (uint32_t)(((ks * 2 + ca) ^ sA) << 4);
            const uint32_t bc = (uint32_t)(((ks * 2 + cb) ^ sB) << 4);
            #pragma unroll
            for (int mf = 0; mf < 4; ++mf) {
                uint32_t ra = stb + T_AH + (uint32_t)((a_row + mf * 16) * 64) + ac;
                LDM_X4(ah[mf], ra);
                LDM_X4(al[mf], ra + (T_AL - T_AH));
            }
            #pragma unroll
            for (int p = 0; p < 2; ++p) {
                uint32_t rb = stb + T_BH + (uint32_t)((b_row + p * 16) * 64) + bc;
                LDM_X4(bh[p], rb);
                if (!isV) LDM_X4(bl[p], rb + (T_BL - T_BH));
            }
            if (!isV) {
                #pragma unroll
                for (int mf = 0; mf < 4; ++mf)
                    #pragma unroll
                    for (int nf = 0; nf < 4; ++nf) {
                        const int p = nf >> 1, hh = (nf & 1) * 2;
                        MMA_BF16(c[mf][nf], ah[mf], bh[p][hh], bh[p][hh+1]);
                        MMA_BF16(c[mf][nf], ah[mf], bl[p][hh], bl[p][hh+1]);
                        MMA_BF16(c[mf][nf], al[mf], bh[p][hh], bh[p][hh+1]);
                    }
            } else {
                #pragma unroll
                for (int mf = 0; mf < 4; ++mf)
                    #pragma unroll
                    for (int nf = 0; nf < 4; ++nf) {
                        const int p = nf >> 1, hh = (nf & 1) * 2;
                        MMA_F16(c[mf][nf], ah[mf][0], ah[mf][1], ah[mf][2], ah[mf][3],
                                bh[p][hh], bh[p][hh+1]);
                        MMA_F16(c[mf][nf], al[mf][0], al[mf][1], al[mf][2], al[mf][3],
                                bh[p][hh], bh[p][hh+1]);
                    }
            }
        }
    }

    __nv_bfloat16* Oh = (proj == 0) ? Qhi : Khi;
    __nv_bfloat16* Ol = (proj == 0) ? Qlo : Klo;

    #pragma unroll
    for (int mf = 0; mf < 4; ++mf) {
        int m0 = bm + warp_m * 64 + mf * 16 + (lane >> 2);
        #pragma unroll
        for (int nf = 0; nf < 4; ++nf) {
            int n = bn + warp_n * 32 + nf * 8 + (lane & 3) * 2;
            float2 bb = *(const float2*)&bias[n];
            float v0 = (c[mf][nf][0] + bb.x) * oscale, v1 = (c[mf][nf][1] + bb.y) * oscale;
            float v2 = (c[mf][nf][2] + bb.x) * oscale, v3 = (c[mf][nf][3] + bb.y) * oscale;
            size_t i0 = (size_t)m0 * DD + n, i1 = (size_t)(m0 + 8) * DD + n;
            if (isV) {
                *(__half2*)&Vh[i0] = __floats2half2_rn(v0, v1);
                *(__half2*)&Vh[i1] = __floats2half2_rn(v2, v3);
            } else {
                __nv_bfloat16 h0 = __float2bfloat16_rn(v0), h1 = __float2bfloat16_rn(v1);
                __nv_bfloat16 h2 = __float2bfloat16_rn(v2), h3 = __float2bfloat16_rn(v3);
                __nv_bfloat162 H0; H0.x = h0; H0.y = h1;
                __nv_bfloat162 H1; H1.x = h2; H1.y = h3;
                __nv_bfloat162 L0, L1;
                L0.x = __float2bfloat16_rn(v0 - __bfloat162float(h0));
                L0.y = __float2bfloat16_rn(v1 - __bfloat162float(h1));
                L1.x = __float2bfloat16_rn(v2 - __bfloat162float(h2));
                L1.y = __float2bfloat16_rn(v3 - __bfloat162float(h3));
                *(__nv_bfloat162*)&Oh[i0] = H0; *(__nv_bfloat162*)&Oh[i1] = H1;
                *(__nv_bfloat162*)&Ol[i0] = L0; *(__nv_bfloat162*)&Ol[i1] = L1;
            }
        }
    }
}

// ============ fp16 2-MMA out GEMM: X(fp16 hi/lo) @ Wo(fp16) + bias ============
#define O_AH 0
#define O_AL 8192
#define O_B  16384
#define O_STAGE 24576
#define OUT_SMEM (3*O_STAGE)

__device__ __forceinline__ void load_chunk_o(
    uint32_t sbase, int st,
    const __half* __restrict__ Xh, const __half* __restrict__ Xl,
    const __half* __restrict__ W16,
    int bm, int bn, int k0, int tid)
{
    uint32_t s = sbase + st * O_STAGE;
    #pragma unroll
    for (int it = 0; it < 2; ++it) {
        int idx = tid + it * 256;
        int row = idx >> 2, q = idx & 3;
        int qs = q ^ ((row >> 1) & 3);
        uint32_t doff = (uint32_t)(row * 64 + qs * 16);
        size_t ga = (size_t)(bm + row) * DD + k0 + q * 8;
        size_t gb = (size_t)(bn + row) * DD + k0 + q * 8;
        cp_async16(s + O_AH + doff, Xh + ga);
        cp_async16(s + O_AL + doff, Xl + ga);
        cp_async16(s + O_B  + doff, W16 + gb);
    }
    CP_COMMIT();
}

__global__ __launch_bounds__(256, 2) void out_gemm(
    const __half* __restrict__ Xh, const __half* __restrict__ Xl,
    const __half* __restrict__ W16,
    const float* __restrict__ bias, float* __restrict__ C)
{
    extern __shared__ char smem[];
    const uint32_t sbase = smem_u32(smem);
    const int tid = threadIdx.x, wid = tid >> 5, lane = tid & 31;
    const int warp_m = wid & 1, warp_n = wid >> 1;
    const int bm = blockIdx.y * 128, bn = blockIdx.x * 128;

    const int a_row = warp_m * 64 + (lane & 15);
    const int sA = (a_row >> 1) & 3;
    const int b_row = warp_n * 32 + ((lane >> 4) << 3) + (lane & 7);
    const int sB = (b_row >> 1) & 3;
    const int ca = (lane >> 4);
    const int cb = ((lane >> 3) & 1);

    float c[4][4][4];
    #pragma unroll
    for (int i = 0; i < 4; ++i)
        #pragma unroll
        for (int j = 0; j < 4; ++j)
            #pragma unroll
            for (int e = 0; e < 4; ++e) c[i][j][e] = 0.f;

    load_chunk_o(sbase, 0, Xh, Xl, W16, bm, bn, 0,  tid);
    load_chunk_o(sbase, 1, Xh, Xl, W16, bm, bn, 32, tid);

    const int NCHUNK = DD / 32;
    for (int i = 0; i < NCHUNK; ++i) {
        const int st = i % 3;
        if (i < NCHUNK - 1) asm volatile("cp.async.wait_group 1;" ::: "memory");
        else                asm volatile("cp.async.wait_group 0;" ::: "memory");
        __syncthreads();
        if (i + 2 < NCHUNK)
            load_chunk_o(sbase, (i + 2) % 3, Xh, Xl, W16, bm, bn, (i + 2) * 32, tid);

        const uint32_t stb = sbase + st * O_STAGE;
        #pragma unroll
        for (int ks = 0; ks < 2; ++ks) {
            uint32_t ah[4][4], al[4][4], bh[2][4];
            const uint32_t ac = (uint32_t)(((ks * 2 + ca) ^ sA) << 4);
            const uint32_t bc = (uint32_t)(((ks * 2 + cb) ^ sB) << 4);
            #pragma unroll
            for (int mf = 0; mf < 4; ++mf) {
                uint32_t ra = stb + O_AH + (uint32_t)((a_row + mf * 16) * 64) + ac;
                LDM_X4(ah[mf], ra);
                LDM_X4(al[mf], ra + (O_AL - O_AH));
            }
            #pragma unroll
            for (int p = 0; p < 2; ++p) {
                uint32_t rb = stb + O_B + (uint32_t)((b_row + p * 16) * 64) + bc;
                LDM_X4(bh[p], rb);
            }
            #pragma unroll
            for (int mf = 0; mf < 4; ++mf)
                #pragma unroll
                for (int nf = 0; nf < 4; ++nf) {
                    const int p = nf >> 1, hh = (nf & 1) * 2;
                    MMA_F16(c[mf][nf], ah[mf][0], ah[mf][1], ah[mf][2], ah[mf][3],
                            bh[p][hh], bh[p][hh+1]);
                    MMA_F16(c[mf][nf], al[mf][0], al[mf][1], al[mf][2], al[mf][3],
                            bh[p][hh], bh[p][hh+1]);
                }
        }
    }

    #pragma unroll
    for (int mf = 0; mf < 4; ++mf) {
        int m0 = bm + warp_m * 64 + mf * 16 + (lane >> 2);
        #pragma unroll
        for (int nf = 0; nf < 4; ++nf) {
            int n = bn + warp_n * 32 + nf * 8 + (lane & 3) * 2;
            float2 bb = *(const float2*)&bias[n];
            *(float2*)&C[(size_t)m0 * DD + n] =
                make_float2(c[mf][nf][0] + bb.x, c[mf][nf][1] + bb.y);
            *(float2*)&C[(size_t)(m0 + 8) * DD + n] =
                make_float2(c[mf][nf][2] + bb.x, c[mf][nf][3] + bb.y);
        }
    }
}

// ============ flash attention: 2-stage 128-key KV ring (stage0 overlays Q) ============
#define AKH 0
#define AKL 16384
#define AKV 32768
#define AST 49152
#define ATTN_SMEM (2*AST)

__device__ __forceinline__ void load_kv128(uint32_t stage_base,
    const char* Khb, const char* Klb, const char* Vhb, int key0, int tid)
{
    #pragma unroll
    for (int p = 0; p < 4; ++p) {
        int id = tid + p * 256;
        int row = id >> 3, c = id & 7;
        int cs = c ^ (row & 7);
        size_t go = (size_t)(key0 + row) * (DD * 2) + c * 16;
        uint32_t so = (uint32_t)(row * 128 + cs * 16);
        cp_async16(stage_base + AKH + so, Khb + go);
        cp_async16(stage_base + AKL + so, Klb + go);
        cp_async16(stage_base + AKV + so, Vhb + go);
    }
    CP_COMMIT();
}

__global__ __launch_bounds__(256, 2) void attn_kernel(
    const __nv_bfloat16* __restrict__ Qh, const __nv_bfloat16* __restrict__ Ql,
    const __nv_bfloat16* __restrict__ Kh, const __nv_bfloat16* __restrict__ Kl,
    const __half* __restrict__ Vv,
    __half* __restrict__ Xh, __half* __restrict__ Xl)
{
    extern __shared__ char sm[];
    const uint32_t sb = smem_u32(sm);
    const int tid = threadIdx.x, lane = tid & 31, w = tid >> 5;
    const int q0 = blockIdx.x * 128;
    const int b = blockIdx.y >> 4, h = blockIdx.y & 15;
    const int g = lane >> 2, qr = lane & 3;
    const int wrow = w * 16;

    const char* Qhb = (const char*)(Qh + (size_t)b * SS * DD + h * 64);
    const char* Qlb = (const char*)(Ql + (size_t)b * SS * DD + h * 64);
    const char* Khb = (const char*)(Kh + (size_t)b * SS * DD + h * 64);
    const char* Klb = (const char*)(Kl + (size_t)b * SS * DD + h * 64);
    const char* Vhb = (const char*)(Vv + (size_t)b * SS * DD + h * 64);

    #pragma unroll
    for (int p = 0; p < 4; ++p) {
        int id = tid + p * 256;
        int row = id >> 3, c = id & 7;
        int cs = c ^ (row & 7);
        size_t go = (size_t)(q0 + row) * (DD * 2) + c * 16;
        uint32_t so = (uint32_t)(row * 128 + cs * 16);
        cp_async16(sb + 0 + so, Qhb + go);
        cp_async16(sb + 16384 + so, Qlb + go);
    }
    CP_COMMIT();

    asm volatile("cp.async.wait_group 0;" ::: "memory");
    __syncthreads();
    const int q_row = wrow + (lane & 15);
    const int kq = q_row & 7;
    const int ca = lane >> 4;
    uint32_t qh[4][4], ql[4][4];
    #pragma unroll
    for (int kc = 0; kc < 4; ++kc) {
        uint32_t ra = sb + (uint32_t)(q_row * 128 + (((kc * 2 + ca) ^ kq) << 4));
        LDM_X4(qh[kc], ra);
        LDM_X4(ql[kc], ra + 16384);
    }
    __syncthreads();
    load_kv128(sb, Khb, Klb, Vhb, 0, tid);

    const int k_rowb = ((lane >> 4) << 3) + (lane & 7);
    const int kk = lane & 7;
    const int cb = (lane >> 3) & 1;
    const int v_row = (((lane >> 3) & 1) << 3) + (lane & 7);
    const int kv_key = lane & 7;
    const int cv = lane >> 4;

    float m0 = -1e30f, m1 = -1e30f, l0 = 0.f, l1 = 0.f;
    float o[8][4];
    #pragma unroll
    for (int j = 0; j < 8; ++j)
        #pragma unroll
        for (int e = 0; e < 4; ++e) o[j][e] = 0.f;

    const int NK = SS / 128;
    for (int kt = 0; kt < NK; ++kt) {
        asm volatile("cp.async.wait_group 0;" ::: "memory");
        __syncthreads();
        if (kt + 1 < NK)
            load_kv128(sb + (uint32_t)(((kt + 1) & 1) * AST),
                       Khb, Klb, Vhb, (kt + 1) * 128, tid);

        const uint32_t STb = sb + (uint32_t)((kt & 1) * AST);

        #pragma unroll
        for (int half = 0; half < 2; ++half) {
            const int rbase = half * 64;

            float s[8][4];
            #pragma unroll
            for (int j = 0; j < 8; ++j)
                #pragma unroll
                for (int e = 0; e < 4; ++e) s[j][e] = 0.f;

            #pragma unroll
            for (int kc = 0; kc < 4; ++kc) {
                const uint32_t kcol = (uint32_t)((((kc * 2 + cb) ^ kk) << 4));
                #pragma unroll
                for (int p = 0; p < 4; ++p) {
                    uint32_t rb = STb + AKH
                        + (uint32_t)((rbase + k_rowb + p * 16) * 128) + kcol;
                    uint32_t kh4[4], kl4[4];
                    LDM_X4(kh4, rb);
                    LDM_X4(kl4, rb + (AKL - AKH));
                    MMA_BF16(s[2*p],   qh[kc], kh4[0], kh4[1]);
                    MMA_BF16(s[2*p],   qh[kc], kl4[0], kl4[1]);
                    MMA_BF16(s[2*p],   ql[kc], kh4[0], kh4[1]);
                    MMA_BF16(s[2*p+1], qh[kc], kh4[2], kh4[3]);
                    MMA_BF16(s[2*p+1], qh[kc], kl4[2], kl4[3]);
                    MMA_BF16(s[2*p+1], ql[kc], kh4[2], kh4[3]);
                }
            }

            float mx0 = -1e30f, mx1 = -1e30f;
            #pragma unroll
            for (int j = 0; j < 8; ++j) {
                mx0 = fmaxf(mx0, fmaxf(s[j][0], s[j][1]));
                mx1 = fmaxf(mx1, fmaxf(s[j][2], s[j][3]));
            }
            mx0 = fmaxf(mx0, __shfl_xor_sync(0xffffffffu, mx0, 1));
            mx0 = fmaxf(mx0, __shfl_xor_sync(0xffffffffu, mx0, 2));
            mx1 = fmaxf(mx1, __shfl_xor_sync(0xffffffffu, mx1, 1));
            mx1 = fmaxf(mx1, __shfl_xor_sync(0xffffffffu, mx1, 2));
            float m0n = fmaxf(m0, mx0), m1n = fmaxf(m1, mx1);
            bool nore = __all_sync(0xffffffffu, (m0n == m0) && (m1n == m1));
            if (!nore) {
                float sc0 = ex2(m0 - m0n), sc1 = ex2(m1 - m1n);
                l0 *= sc0; l1 *= sc1;
                #pragma unroll
                for (int j = 0; j < 8; ++j) {
                    o[j][0] *= sc0; o[j][1] *= sc0;
                    o[j][2] *= sc1; o[j][3] *= sc1;
                }
            }
            m0 = m0n; m1 = m1n;

            const uint32_t vbase = STb + AKV;
            #pragma unroll
            for (int kc = 0; kc < 4; ++kc) {
                const int j0 = 2 * kc, j1 = 2 * kc + 1;
                float e00 = ex2(s[j0][0] - m0n), e01 = ex2(s[j0][1] - m0n);
                float e02 = ex2(s[j0][2] - m1n), e03 = ex2(s[j0][3] - m1n);
                float e10 = ex2(s[j1][0] - m0n), e11 = ex2(s[j1][1] - m0n);
                float e12 = ex2(s[j1][2] - m1n), e13 = ex2(s[j1][3] - m1n);
                l0 += e00 + e01 + e10 + e11;
                l1 += e02 + e03 + e12 + e13;
                uint32_t a0 = f2h2(e00, e01);
                uint32_t a1 = f2h2(e02, e03);
                uint32_t a2 = f2h2(e10, e11);
                uint32_t a3 = f2h2(e12, e13);
                const int mrow = rbase + kc * 16 + v_row;
                #pragma unroll
                for (int nfp = 0; nfp < 4; ++nfp) {
                    const int nf = 2 * nfp;
                    uint32_t addr = vbase + (uint32_t)(mrow * 128
                                     + (((nf + cv) ^ kv_key) << 4));
                    uint32_t r0, r1, r2, r3;
                    asm volatile("ldmatrix.sync.aligned.m8n8.x4.trans.shared.b16 {%0,%1,%2,%3}, [%4];"
                        : "=r"(r0), "=r"(r1), "=r"(r2), "=r"(r3) : "r"(addr));
                    MMA_F16(o[nf],     a0, a1, a2, a3, r0, r1);
                    MMA_F16(o[nf + 1], a0, a1, a2, a3, r2, r3);
                }
            }
        }
    }

    l0 += __shfl_xor_sync(0xffffffffu, l0, 1);
    l0 += __shfl_xor_sync(0xffffffffu, l0, 2);
    l1 += __shfl_xor_sync(0xffffffffu, l1, 1);
    l1 += __shfl_xor_sync(0xffffffffu, l1, 2);

    float inv0 = 1.0f / l0, inv1 = 1.0f / l1;
    size_t r0g = ((size_t)(h * BB + b) * SS + q0 + wrow + g) * 64;
    size_t r1g = r0g + 8 * 64;
    #pragma unroll
    for (int nf = 0; nf < 8; ++nf) {
        int col = nf * 8 + qr * 2;
        float v0 = o[nf][0] * inv0, v1 = o[nf][1] * inv0;
        float v2 = o[nf][2] * inv1, v3 = o[nf][3] * inv1;
        __half h0 = __float2half_rn(v0), h1 = __float2half_rn(v1);
        __half h2 = __float2half_rn(v2), h3 = __float2half_rn(v3);
        __half2 H0; H0.x = h0; H0.y = h1;
        __half2 H1; H1.x = h2; H1.y = h3;
        __half2 L0, L1;
        L0.x = __float2half_rn(v0 - __half2float(h0));
        L0.y = __float2half_rn(v1 - __half2float(h1));
        L1.x = __float2half_rn(v2 - __half2float(h2));
        L1.y = __float2half_rn(v3 - __half2float(h3));
        *(__half2*)&Xh[r0g + col] = H0;
        *(__half2*)&Xh[r1g + col] = H1;
        *(__half2*)&Xl[r0g + col] = L0;
        *(__half2*)&Xl[r1g + col] = L1;
    }
}

extern "C" void kernel_launch(void* const* d_in, const int* in_sizes, int n_in,
                              void* d_out, int out_size)
{
    const float* q  = (const float*)d_in[0];
    const float* k  = (const float*)d_in[1];
    const float* v  = (const float*)d_in[2];
    const float* wq = (const float*)d_in[3];
    const float* bq = (const float*)d_in[4];
    const float* wk = (const float*)d_in[5];
    const float* bk = (const float*)d_in[6];
    const float* wv = (const float*)d_in[7];
    const float* bv = (const float*)d_in[8];
    const float* wo = (const float*)d_in[9];
    const float* bo = (const float*)d_in[10];
    float* out = (float*)d_out;

    __nv_bfloat16 *Whi, *Wlo, *Ahi, *Alo, *Qhi, *Qlo, *Khi, *Klo;
    __half *Vh, *Xh, *Xl;
    cudaGetSymbolAddress((void**)&Whi, g_Whi);
    cudaGetSymbolAddress((void**)&Wlo, g_Wlo);
    cudaGetSymbolAddress((void**)&Ahi, g_Ahi);
    cudaGetSymbolAddress((void**)&Alo, g_Alo);
    cudaGetSymbolAddress((void**)&Qhi, g_Qhi);
    cudaGetSymbolAddress((void**)&Qlo, g_Qlo);
    cudaGetSymbolAddress((void**)&Khi, g_Khi);
    cudaGetSymbolAddress((void**)&Klo, g_Klo);
    cudaGetSymbolAddress((void**)&Vh,  g_Vh);
    cudaGetSymbolAddress((void**)&Xh,  g_Xh16);
    cudaGetSymbolAddress((void**)&Xl,  g_Xl16);

    cudaFuncSetAttribute(qkv_gemm,    cudaFuncAttributeMaxDynamicSharedMemorySize, GEMM_SMEM);
    cudaFuncSetAttribute(out_gemm,    cudaFuncAttributeMaxDynamicSharedMemorySize, OUT_SMEM);
    cudaFuncSetAttribute(attn_kernel, cudaFuncAttributeMaxDynamicSharedMemorySize, ATTN_SMEM);

    dim3 pGrid(MTOT * DD / 4 / 256, 1, 4);
    pre_kernel<<<pGrid, 256>>>(q, k, v, wq, wk, wv, wo, Ahi, Alo, Whi, Wlo);

    dim3 qkvGrid(24, MTOT / 128);
    qkv_gemm<<<qkvGrid, 256, GEMM_SMEM>>>(Ahi, Alo, Whi, Wlo, bq, bk, bv,
                                          Qhi, Qlo, Khi, Klo, Vh);

    dim3 aGrid(SS / 128, BB * HH);
    attn_kernel<<<aGrid, 256, ATTN_SMEM>>>(Qhi, Qlo, Khi, Klo, Vh, Xh, Xl);

    dim3 oGrid(DD / 128, MTOT / 128);
    out_gemm<<<oGrid, 256, OUT_SMEM>>>(Xh, Xl, (const __half*)(Whi + 3*(size_t)DD*DD),
                                       bo, out);
}

// round 16
// speedup vs baseline: 1.1630x; 1.0732x over previous
#include <cuda_runtime.h>
#include <cuda_bf16.h>
#include <cuda_fp16.h>
#include <cstdint>
#include <math.h>

#define BB 2
#define SS 2048
#define DD 1024
#define HH 16
#define DHH 64
#define MTOT (BB*SS)
#define LOG2E 1.44269504088896f

// Whi plane 2 = Wv fp16, plane 3 = Wo fp16. Ahi plane 2 = v act fp16 (single).
__device__ __align__(256) __nv_bfloat16 g_Whi[4][DD*DD];
__device__ __align__(256) __nv_bfloat16 g_Wlo[2][DD*DD];
__device__ __align__(256) __nv_bfloat16 g_Ahi[3][MTOT*DD];
__device__ __align__(256) __nv_bfloat16 g_Alo[2][MTOT*DD];
__device__ __align__(256) __nv_bfloat16 g_Qhi[MTOT*DD];
__device__ __align__(256) __nv_bfloat16 g_Qlo[MTOT*DD];
__device__ __align__(256) __nv_bfloat16 g_Khi[MTOT*DD];
__device__ __align__(256) __nv_bfloat16 g_Klo[MTOT*DD];
__device__ __align__(256) __half        g_Vh [MTOT*DD];
__device__ __align__(256) __half        g_Xh16[MTOT*DD];

__device__ __forceinline__ uint32_t smem_u32(const void* p) {
    uint32_t a;
    asm("{ .reg .u64 t; cvta.to.shared.u64 t, %1; cvt.u32.u64 %0, t; }" : "=r"(a) : "l"(p));
    return a;
}
__device__ __forceinline__ void cp_async16(uint32_t dst, const void* src) {
    asm volatile("cp.async.cg.shared.global [%0], [%1], 16;" :: "r"(dst), "l"(src));
}
#define CP_COMMIT() asm volatile("cp.async.commit_group;" ::: "memory")

#define MMA_BF16(c, a, b0, b1) \
    asm volatile("mma.sync.aligned.m16n8k16.row.col.f32.bf16.bf16.f32 " \
        "{%0,%1,%2,%3}, {%4,%5,%6,%7}, {%8,%9}, {%0,%1,%2,%3};" \
        : "+f"((c)[0]), "+f"((c)[1]), "+f"((c)[2]), "+f"((c)[3]) \
        : "r"((a)[0]), "r"((a)[1]), "r"((a)[2]), "r"((a)[3]), "r"(b0), "r"(b1))

#define MMA_F16(c, a0, a1, a2, a3, b0, b1) \
    asm volatile("mma.sync.aligned.m16n8k16.row.col.f32.f16.f16.f32 " \
        "{%0,%1,%2,%3}, {%4,%5,%6,%7}, {%8,%9}, {%0,%1,%2,%3};" \
        : "+f"((c)[0]), "+f"((c)[1]), "+f"((c)[2]), "+f"((c)[3]) \
        : "r"(a0), "r"(a1), "r"(a2), "r"(a3), "r"(b0), "r"(b1))

#define LDM_X4(r, a) \
    asm volatile("ldmatrix.sync.aligned.m8n8.x4.shared.b16 {%0,%1,%2,%3}, [%4];" \
        : "=r"((r)[0]), "=r"((r)[1]), "=r"((r)[2]), "=r"((r)[3]) : "r"(a))

__device__ __forceinline__ uint32_t f2h2(float x, float y) {
    __half2 t = __floats2half2_rn(x, y);
    return *(uint32_t*)&t;
}
__device__ __forceinline__ float ex2(float x) {
    float y;
    asm("ex2.approx.ftz.f32 %0, %1;" : "=f"(y) : "f"(x));
    return y;
}

// ============ fused prologue ============
// z==0,1: bf16 hi/lo split of q,k. z==2: single fp16 convert of v.
// z==3: weight transposes; wsel 0,1 bf16 hi/lo; wsel 2 (Wv), 3 (Wo) single fp16.
__global__ __launch_bounds__(256) void pre_kernel(
    const float* __restrict__ a0, const float* __restrict__ a1,
    const float* __restrict__ a2,
    const float* __restrict__ w0, const float* __restrict__ w1,
    const float* __restrict__ w2, const float* __restrict__ w3,
    __nv_bfloat16* __restrict__ Ahi_base, __nv_bfloat16* __restrict__ Alo_base,
    __nv_bfloat16* __restrict__ Whi_base, __nv_bfloat16* __restrict__ Wlo_base)
{
    if (blockIdx.z < 3) {
        int i = blockIdx.x * 256 + threadIdx.x;
        const float* a = (blockIdx.z == 0) ? a0 : (blockIdx.z == 1) ? a1 : a2;
        float4 v = ((const float4*)a)[i];
        if (blockIdx.z == 2) {
            __half* a16 = (__half*)(Ahi_base + 2 * (size_t)MTOT * DD);
            ((__half2*)a16)[i*2+0] = __floats2half2_rn(v.x, v.y);
            ((__half2*)a16)[i*2+1] = __floats2half2_rn(v.z, v.w);
        } else {
            __nv_bfloat16* hi = Ahi_base + (size_t)blockIdx.z * MTOT * DD;
            __nv_bfloat16* lo = Alo_base + (size_t)blockIdx.z * MTOT * DD;
            __nv_bfloat16 hx = __float2bfloat16_rn(v.x), hy = __float2bfloat16_rn(v.y);
            __nv_bfloat16 hz = __float2bfloat16_rn(v.z), hw = __float2bfloat16_rn(v.w);
            __nv_bfloat162 h0; h0.x = hx; h0.y = hy;
            __nv_bfloat162 h1; h1.x = hz; h1.y = hw;
            __nv_bfloat162 l0, l1;
            l0.x = __float2bfloat16_rn(v.x - __bfloat162float(hx));
            l0.y = __float2bfloat16_rn(v.y - __bfloat162float(hy));
            l1.x = __float2bfloat16_rn(v.z - __bfloat162float(hz));
            l1.y = __float2bfloat16_rn(v.w - __bfloat162float(hw));
            ((__nv_bfloat162*)hi)[i*2+0] = h0; ((__nv_bfloat162*)hi)[i*2+1] = h1;
            ((__nv_bfloat162*)lo)[i*2+0] = l0; ((__nv_bfloat162*)lo)[i*2+1] = l1;
        }
    } else {
        int wsel = blockIdx.x >> 10;
        int tile = blockIdx.x & 1023;
        int bx = tile & 31, by = tile >> 5;
        const float* in = (wsel == 0) ? w0 : (wsel == 1) ? w1 : (wsel == 2) ? w2 : w3;
        __shared__ float t[32][33];
        int tx = threadIdx.x & 31, ty = threadIdx.x >> 5;
        int x = bx * 32 + tx;
        int y = by * 32 + ty;
        #pragma unroll
        for (int j = 0; j < 32; j += 8)
            t[ty + j][tx] = in[(size_t)(y + j) * DD + x];
        __syncthreads();
        int x2 = by * 32 + tx;
        int y2 = bx * 32 + ty;
        if (wsel >= 2) {
            __half* w16 = (__half*)(Whi_base + (size_t)wsel * DD * DD);
            #pragma unroll
            for (int j = 0; j < 32; j += 8)
                w16[(size_t)(y2 + j) * DD + x2] = __float2half_rn(t[tx][ty + j]);
        } else {
            __nv_bfloat16* hi = Whi_base + (size_t)wsel * DD * DD;
            __nv_bfloat16* lo = Wlo_base + (size_t)wsel * DD * DD;
            #pragma unroll
            for (int j = 0; j < 32; j += 8) {
                float w = t[tx][ty + j];
                __nv_bfloat16 h = __float2bfloat16_rn(w);
                hi[(size_t)(y2 + j) * DD + x2] = h;
                lo[(size_t)(y2 + j) * DD + x2] = __float2bfloat16_rn(w - __bfloat162float(h));
            }
        }
    }
}

// ============ fused QKV GEMM: 128x128, 3-stage, occ 2 ============
// proj 0,1: split-bf16 x split-bf16 (3 MMAs). proj 2: fp16 x fp16 (1 MMA).
#define T_AH    0
#define T_AL    8192
#define T_BH    16384
#define T_BL    24576
#define STAGE   32768
#define GEMM_SMEM (3*STAGE)

__device__ __forceinline__ void load_chunk_g(
    uint32_t sbase, int st,
    const __nv_bfloat16* __restrict__ Ah, const __nv_bfloat16* __restrict__ Al,
    const __nv_bfloat16* __restrict__ Bh, const __nv_bfloat16* __restrict__ Bl,
    int bm, int bn, int k0, int tid, bool full)
{
    uint32_t s = sbase + st * STAGE;
    #pragma unroll
    for (int it = 0; it < 2; ++it) {
        int idx = tid + it * 256;
        int row = idx >> 2, q = idx & 3;
        int qs = q ^ ((row >> 1) & 3);
        uint32_t doff = (uint32_t)(row * 64 + qs * 16);
        size_t ga = (size_t)(bm + row) * DD + k0 + q * 8;
        size_t gb = (size_t)(bn + row) * DD + k0 + q * 8;
        cp_async16(s + T_AH + doff, Ah + ga);
        cp_async16(s + T_BH + doff, Bh + gb);
        if (full) {
            cp_async16(s + T_AL + doff, Al + ga);
            cp_async16(s + T_BL + doff, Bl + gb);
        }
    }
    CP_COMMIT();
}

__global__ __launch_bounds__(256, 2) void qkv_gemm(
    const __nv_bfloat16* __restrict__ Ahi_all, const __nv_bfloat16* __restrict__ Alo_all,
    const __nv_bfloat16* __restrict__ Whi_all, const __nv_bfloat16* __restrict__ Wlo_all,
    const float* __restrict__ bq, const float* __restrict__ bk, const float* __restrict__ bv,
    __nv_bfloat16* __restrict__ Qhi, __nv_bfloat16* __restrict__ Qlo,
    __nv_bfloat16* __restrict__ Khi, __nv_bfloat16* __restrict__ Klo,
    __half* __restrict__ Vh)
{
    extern __shared__ char smem[];
    const uint32_t sbase = smem_u32(smem);
    const int tid = threadIdx.x, wid = tid >> 5, lane = tid & 31;
    const int warp_m = wid & 1, warp_n = wid >> 1;
    const int proj = blockIdx.x >> 3;
    const int bn = (blockIdx.x & 7) * 128;
    const int bm = blockIdx.y * 128;
    const bool isV = (proj == 2);

    const __nv_bfloat16* Ah = Ahi_all + (size_t)proj * MTOT * DD;
    const __nv_bfloat16* Al = Alo_all + (size_t)(isV ? 0 : proj) * MTOT * DD;  // unused for V
    const __nv_bfloat16* Bh = Whi_all + (size_t)proj * DD * DD;
    const __nv_bfloat16* Bl = Wlo_all + (size_t)(isV ? 0 : proj) * DD * DD;    // unused for V
    const float* bias = (proj == 0) ? bq : (proj == 1) ? bk : bv;
    const float oscale = (proj == 0) ? LOG2E : 1.0f;

    const int a_row = warp_m * 64 + (lane & 15);
    const int sA = (a_row >> 1) & 3;
    const int b_row = warp_n * 32 + ((lane >> 4) << 3) + (lane & 7);
    const int sB = (b_row >> 1) & 3;
    const int ca = (lane >> 4);
    const int cb = ((lane >> 3) & 1);

    float c[4][4][4];
    #pragma unroll
    for (int i = 0; i < 4; ++i)
        #pragma unroll
        for (int j = 0; j < 4; ++j)
            #pragma unroll
            for (int e = 0; e < 4; ++e) c[i][j][e] = 0.f;

    load_chunk_g(sbase, 0, Ah, Al, Bh, Bl, bm, bn, 0,  tid, !isV);
    load_chunk_g(sbase, 1, Ah, Al, Bh, Bl, bm, bn, 32, tid, !isV);

    const int NCHUNK = DD / 32;
    for (int i = 0; i < NCHUNK; ++i) {
        const int st = i % 3;
        if (i < NCHUNK - 1) asm volatile("cp.async.wait_group 1;" ::: "memory");
        else                asm volatile("cp.async.wait_group 0;" ::: "memory");
        __syncthreads();
        if (i + 2 < NCHUNK)
            load_chunk_g(sbase, (i + 2) % 3, Ah, Al, Bh, Bl, bm, bn, (i + 2) * 32, tid, !isV);

        const uint32_t stb = sbase + st * STAGE;
        #pragma unroll
        for (int ks = 0; ks < 2; ++ks) {
            uint32_t ah[4][4], al[4][4], bh[2][4], bl[2][4];
            const uint32_t ac = (uint32_t)(((ks * 2 + ca) ^ sA) << 4);
            const uint32_t bc = (uint32_t)(((ks * 2 + cb) ^ sB) << 4);
            #pragma unroll
            for (int mf = 0; mf < 4; ++mf) {
                uint32_t ra = stb + T_AH + (uint32_t)((a_row + mf * 16) * 64) + ac;
                LDM_X4(ah[mf], ra);
                if (!isV) LDM_X4(al[mf], ra + (T_AL - T_AH));
            }
            #pragma unroll
            for (int p = 0; p < 2; ++p) {
                uint32_t rb = stb + T_BH + (uint32_t)((b_row + p * 16) * 64) + bc;
                LDM_X4(bh[p], rb);
                if (!isV) LDM_X4(bl[p], rb + (T_BL - T_BH));
            }
            if (!isV) {
                #pragma unroll
                for (int mf = 0; mf < 4; ++mf)
                    #pragma unroll
                    for (int nf = 0; nf < 4; ++nf) {
                        const int p = nf >> 1, hh = (nf & 1) * 2;
                        MMA_BF16(c[mf][nf], ah[mf], bh[p][hh], bh[p][hh+1]);
                        MMA_BF16(c[mf][nf], ah[mf], bl[p][hh], bl[p][hh+1]);
                        MMA_BF16(c[mf][nf], al[mf], bh[p][hh], bh[p][hh+1]);
                    }
            } else {
                #pragma unroll
                for (int mf = 0; mf < 4; ++mf)
                    #pragma unroll
                    for (int nf = 0; nf < 4; ++nf) {
                        const int p = nf >> 1, hh = (nf & 1) * 2;
                        MMA_F16(c[mf][nf], ah[mf][0], ah[mf][1], ah[mf][2], ah[mf][3],
                                bh[p][hh], bh[p][hh+1]);
                    }
            }
        }
    }

    __nv_bfloat16* Oh = (proj == 0) ? Qhi : Khi;
    __nv_bfloat16* Ol = (proj == 0) ? Qlo : Klo;

    #pragma unroll
    for (int mf = 0; mf < 4; ++mf) {
        int m0 = bm + warp_m * 64 + mf * 16 + (lane >> 2);
        #pragma unroll
        for (int nf = 0; nf < 4; ++nf) {
            int n = bn + warp_n * 32 + nf * 8 + (lane & 3) * 2;
            float2 bb = *(const float2*)&bias[n];
            float v0 = (c[mf][nf][0] + bb.x) * oscale, v1 = (c[mf][nf][1] + bb.y) * oscale;
            float v2 = (c[mf][nf][2] + bb.x) * oscale, v3 = (c[mf][nf][3] + bb.y) * oscale;
            size_t i0 = (size_t)m0 * DD + n, i1 = (size_t)(m0 + 8) * DD + n;
            if (isV) {
                *(__half2*)&Vh[i0] = __floats2half2_rn(v0, v1);
                *(__half2*)&Vh[i1] = __floats2half2_rn(v2, v3);
            } else {
                __nv_bfloat16 h0 = __float2bfloat16_rn(v0), h1 = __float2bfloat16_rn(v1);
                __nv_bfloat16 h2 = __float2bfloat16_rn(v2), h3 = __float2bfloat16_rn(v3);
                __nv_bfloat162 H0; H0.x = h0; H0.y = h1;
                __nv_bfloat162 H1; H1.x = h2; H1.y = h3;
                __nv_bfloat162 L0, L1;
                L0.x = __float2bfloat16_rn(v0 - __bfloat162float(h0));
                L0.y = __float2bfloat16_rn(v1 - __bfloat162float(h1));
                L1.x = __float2bfloat16_rn(v2 - __bfloat162float(h2));
                L1.y = __float2bfloat16_rn(v3 - __bfloat162float(h3));
                *(__nv_bfloat162*)&Oh[i0] = H0; *(__nv_bfloat162*)&Oh[i1] = H1;
                *(__nv_bfloat162*)&Ol[i0] = L0; *(__nv_bfloat162*)&Ol[i1] = L1;
            }
        }
    }
}

// ============ fp16 1-MMA out GEMM: X(fp16) @ Wo(fp16) + bias ============
#define O_A  0
#define O_B  8192
#define O_STAGE 16384
#define OUT_SMEM (3*O_STAGE)   // 49152

__device__ __forceinline__ void load_chunk_o(
    uint32_t sbase, int st,
    const __half* __restrict__ Xh, const __half* __restrict__ W16,
    int bm, int bn, int k0, int tid)
{
    uint32_t s = sbase + st * O_STAGE;
    #pragma unroll
    for (int it = 0; it < 2; ++it) {
        int idx = tid + it * 256;
        int row = idx >> 2, q = idx & 3;
        int qs = q ^ ((row >> 1) & 3);
        uint32_t doff = (uint32_t)(row * 64 + qs * 16);
        size_t ga = (size_t)(bm + row) * DD + k0 + q * 8;
        size_t gb = (size_t)(bn + row) * DD + k0 + q * 8;
        cp_async16(s + O_A + doff, Xh + ga);
        cp_async16(s + O_B + doff, W16 + gb);
    }
    CP_COMMIT();
}

__global__ __launch_bounds__(256, 2) void out_gemm(
    const __half* __restrict__ Xh, const __half* __restrict__ W16,
    const float* __restrict__ bias, float* __restrict__ C)
{
    extern __shared__ char smem[];
    const uint32_t sbase = smem_u32(smem);
    const int tid = threadIdx.x, wid = tid >> 5, lane = tid & 31;
    const int warp_m = wid & 1, warp_n = wid >> 1;
    const int bm = blockIdx.y * 128, bn = blockIdx.x * 128;

    const int a_row = warp_m * 64 + (lane & 15);
    const int sA = (a_row >> 1) & 3;
    const int b_row = warp_n * 32 + ((lane >> 4) << 3) + (lane & 7);
    const int sB = (b_row >> 1) & 3;
    const int ca = (lane >> 4);
    const int cb = ((lane >> 3) & 1);

    float c[4][4][4];
    #pragma unroll
    for (int i = 0; i < 4; ++i)
        #pragma unroll
        for (int j = 0; j < 4; ++j)
            #pragma unroll
            for (int e = 0; e < 4; ++e) c[i][j][e] = 0.f;

    load_chunk_o(sbase, 0, Xh, W16, bm, bn, 0,  tid);
    load_chunk_o(sbase, 1, Xh, W16, bm, bn, 32, tid);

    const int NCHUNK = DD / 32;
    for (int i = 0; i < NCHUNK; ++i) {
        const int st = i % 3;
        if (i < NCHUNK - 1) asm volatile("cp.async.wait_group 1;" ::: "memory");
        else                asm volatile("cp.async.wait_group 0;" ::: "memory");
        __syncthreads();
        if (i + 2 < NCHUNK)
            load_chunk_o(sbase, (i + 2) % 3, Xh, W16, bm, bn, (i + 2) * 32, tid);

        const uint32_t stb = sbase + st * O_STAGE;
        #pragma unroll
        for (int ks = 0; ks < 2; ++ks) {
            uint32_t ah[4][4], bh[2][4];
            const uint32_t ac = (uint32_t)(((ks * 2 + ca) ^ sA) << 4);
            const uint32_t bc = (uint32_t)(((ks * 2 + cb) ^ sB) << 4);
            #pragma unroll
            for (int mf = 0; mf < 4; ++mf) {
                uint32_t ra = stb + O_A + (uint32_t)((a_row + mf * 16) * 64) + ac;
                LDM_X4(ah[mf], ra);
            }
            #pragma unroll
            for (int p = 0; p < 2; ++p) {
                uint32_t rb = stb + O_B + (uint32_t)((b_row + p * 16) * 64) + bc;
                LDM_X4(bh[p], rb);
            }
            #pragma unroll
            for (int mf = 0; mf < 4; ++mf)
                #pragma unroll
                for (int nf = 0; nf < 4; ++nf) {
                    const int p = nf >> 1, hh = (nf & 1) * 2;
                    MMA_F16(c[mf][nf], ah[mf][0], ah[mf][1], ah[mf][2], ah[mf][3],
                            bh[p][hh], bh[p][hh+1]);
                }
        }
    }

    #pragma unroll
    for (int mf = 0; mf < 4; ++mf) {
        int m0 = bm + warp_m * 64 + mf * 16 + (lane >> 2);
        #pragma unroll
        for (int nf = 0; nf < 4; ++nf) {
            int n = bn + warp_n * 32 + nf * 8 + (lane & 3) * 2;
            float2 bb = *(const float2*)&bias[n];
            *(float2*)&C[(size_t)m0 * DD + n] =
                make_float2(c[mf][nf][0] + bb.x, c[mf][nf][1] + bb.y);
            *(float2*)&C[(size_t)(m0 + 8) * DD + n] =
                make_float2(c[mf][nf][2] + bb.x, c[mf][nf][3] + bb.y);
        }
    }
}

// ============ flash attention: 2-stage 128-key KV ring (stage0 overlays Q) ============
#define AKH 0
#define AKL 16384
#define AKV 32768
#define AST 49152
#define ATTN_SMEM (2*AST)

__device__ __forceinline__ void load_kv128(uint32_t stage_base,
    const char* Khb, const char* Klb, const char* Vhb, int key0, int tid)
{
    #pragma unroll
    for (int p = 0; p < 4; ++p) {
        int id = tid + p * 256;
        int row = id >> 3, c = id & 7;
        int cs = c ^ (row & 7);
        size_t go = (size_t)(key0 + row) * (DD * 2) + c * 16;
        uint32_t so = (uint32_t)(row * 128 + cs * 16);
        cp_async16(stage_base + AKH + so, Khb + go);
        cp_async16(stage_base + AKL + so, Klb + go);
        cp_async16(stage_base + AKV + so, Vhb + go);
    }
    CP_COMMIT();
}

__global__ __launch_bounds__(256, 2) void attn_kernel(
    const __nv_bfloat16* __restrict__ Qh, const __nv_bfloat16* __restrict__ Ql,
    const __nv_bfloat16* __restrict__ Kh, const __nv_bfloat16* __restrict__ Kl,
    const __half* __restrict__ Vv, __half* __restrict__ Xh)
{
    extern __shared__ char sm[];
    const uint32_t sb = smem_u32(sm);
    const int tid = threadIdx.x, lane = tid & 31, w = tid >> 5;
    const int q0 = blockIdx.x * 128;
    const int b = blockIdx.y >> 4, h = blockIdx.y & 15;
    const int g = lane >> 2, qr = lane & 3;
    const int wrow = w * 16;

    const char* Qhb = (const char*)(Qh + (size_t)b * SS * DD + h * 64);
    const char* Qlb = (const char*)(Ql + (size_t)b * SS * DD + h * 64);
    const char* Khb = (const char*)(Kh + (size_t)b * SS * DD + h * 64);
    const char* Klb = (const char*)(Kl + (size_t)b * SS * DD + h * 64);
    const char* Vhb = (const char*)(Vv + (size_t)b * SS * DD + h * 64);

    #pragma unroll
    for (int p = 0; p < 4; ++p) {
        int id = tid + p * 256;
        int row = id >> 3, c = id & 7;
        int cs = c ^ (row & 7);
        size_t go = (size_t)(q0 + row) * (DD * 2) + c * 16;
        uint32_t so = (uint32_t)(row * 128 + cs * 16);
        cp_async16(sb + 0 + so, Qhb + go);
        cp_async16(sb + 16384 + so, Qlb + go);
    }
    CP_COMMIT();

    asm volatile("cp.async.wait_group 0;" ::: "memory");
    __syncthreads();
    const int q_row = wrow + (lane & 15);
    const int kq = q_row & 7;
    const int ca = lane >> 4;
    uint32_t qh[4][4], ql[4][4];
    #pragma unroll
    for (int kc = 0; kc < 4; ++kc) {
        uint32_t ra = sb + (uint32_t)(q_row * 128 + (((kc * 2 + ca) ^ kq) << 4));
        LDM_X4(qh[kc], ra);
        LDM_X4(ql[kc], ra + 16384);
    }
    __syncthreads();
    load_kv128(sb, Khb, Klb, Vhb, 0, tid);

    const int k_rowb = ((lane >> 4) << 3) + (lane & 7);
    const int kk = lane & 7;
    const int cb = (lane >> 3) & 1;
    const int v_row = (((lane >> 3) & 1) << 3) + (lane & 7);
    const int kv_key = lane & 7;
    const int cv = lane >> 4;

    float m0 = -1e30f, m1 = -1e30f, l0 = 0.f, l1 = 0.f;
    float o[8][4];
    #pragma unroll
    for (int j = 0; j < 8; ++j)
        #pragma unroll
        for (int e = 0; e < 4; ++e) o[j][e] = 0.f;

    const int NK = SS / 128;
    for (int kt = 0; kt < NK; ++kt) {
        asm volatile("cp.async.wait_group 0;" ::: "memory");
        __syncthreads();
        if (kt + 1 < NK)
            load_kv128(sb + (uint32_t)(((kt + 1) & 1) * AST),
                       Khb, Klb, Vhb, (kt + 1) * 128, tid);

        const uint32_t STb = sb + (uint32_t)((kt & 1) * AST);

        #pragma unroll
        for (int half = 0; half < 2; ++half) {
            const int rbase = half * 64;

            float s[8][4];
            #pragma unroll
            for (int j = 0; j < 8; ++j)
                #pragma unroll
                for (int e = 0; e < 4; ++e) s[j][e] = 0.f;

            #pragma unroll
            for (int kc = 0; kc < 4; ++kc) {
                const uint32_t kcol = (uint32_t)((((kc * 2 + cb) ^ kk) << 4));
                #pragma unroll
                for (int p = 0; p < 4; ++p) {
                    uint32_t rb = STb + AKH
                        + (uint32_t)((rbase + k_rowb + p * 16) * 128) + kcol;
                    uint32_t kh4[4], kl4[4];
                    LDM_X4(kh4, rb);
                    LDM_X4(kl4, rb + (AKL - AKH));
                    MMA_BF16(s[2*p],   qh[kc], kh4[0], kh4[1]);
                    MMA_BF16(s[2*p],   qh[kc], kl4[0], kl4[1]);
                    MMA_BF16(s[2*p],   ql[kc], kh4[0], kh4[1]);
                    MMA_BF16(s[2*p+1], qh[kc], kh4[2], kh4[3]);
                    MMA_BF16(s[2*p+1], qh[kc], kl4[2], kl4[3]);
                    MMA_BF16(s[2*p+1], ql[kc], kh4[2], kh4[3]);
                }
            }

            float mx0 = -1e30f, mx1 = -1e30f;
            #pragma unroll
            for (int j = 0; j < 8; ++j) {
                mx0 = fmaxf(mx0, fmaxf(s[j][0], s[j][1]));
                mx1 = fmaxf(mx1, fmaxf(s[j][2], s[j][3]));
            }
            mx0 = fmaxf(mx0, __shfl_xor_sync(0xffffffffu, mx0, 1));
            mx0 = fmaxf(mx0, __shfl_xor_sync(0xffffffffu, mx0, 2));
            mx1 = fmaxf(mx1, __shfl_xor_sync(0xffffffffu, mx1, 1));
            mx1 = fmaxf(mx1, __shfl_xor_sync(0xffffffffu, mx1, 2));
            float m0n = fmaxf(m0, mx0), m1n = fmaxf(m1, mx1);
            bool nore = __all_sync(0xffffffffu, (m0n == m0) && (m1n == m1));
            if (!nore) {
                float sc0 = ex2(m0 - m0n), sc1 = ex2(m1 - m1n);
                l0 *= sc0; l1 *= sc1;
                #pragma unroll
                for (int j = 0; j < 8; ++j) {
                    o[j][0] *= sc0; o[j][1] *= sc0;
                    o[j][2] *= sc1; o[j][3] *= sc1;
                }
            }
            m0 = m0n; m1 = m1n;

            const uint32_t vbase = STb + AKV;
            #pragma unroll
            for (int kc = 0; kc < 4; ++kc) {
                const int j0 = 2 * kc, j1 = 2 * kc + 1;
                float e00 = ex2(s[j0][0] - m0n), e01 = ex2(s[j0][1] - m0n);
                float e02 = ex2(s[j0][2] - m1n), e03 = ex2(s[j0][3] - m1n);
                float e10 = ex2(s[j1][0] - m0n), e11 = ex2(s[j1][1] - m0n);
                float e12 = ex2(s[j1][2] - m1n), e13 = ex2(s[j1][3] - m1n);
                l0 += e00 + e01 + e10 + e11;
                l1 += e02 + e03 + e12 + e13;
                uint32_t a0 = f2h2(e00, e01);
                uint32_t a1 = f2h2(e02, e03);
                uint32_t a2 = f2h2(e10, e11);
                uint32_t a3 = f2h2(e12, e13);
                const int mrow = rbase + kc * 16 + v_row;
                #pragma unroll
                for (int nfp = 0; nfp < 4; ++nfp) {
                    const int nf = 2 * nfp;
                    uint32_t addr = vbase + (uint32_t)(mrow * 128
                                     + (((nf + cv) ^ kv_key) << 4));
                    uint32_t r0, r1, r2, r3;
                    asm volatile("ldmatrix.sync.aligned.m8n8.x4.trans.shared.b16 {%0,%1,%2,%3}, [%4];"
                        : "=r"(r0), "=r"(r1), "=r"(r2), "=r"(r3) : "r"(addr));
                    MMA_F16(o[nf],     a0, a1, a2, a3, r0, r1);
                    MMA_F16(o[nf + 1], a0, a1, a2, a3, r2, r3);
                }
            }
        }
    }

    l0 += __shfl_xor_sync(0xffffffffu, l0, 1);
    l0 += __shfl_xor_sync(0xffffffffu, l0, 2);
    l1 += __shfl_xor_sync(0xffffffffu, l1, 1);
    l1 += __shfl_xor_sync(0xffffffffu, l1, 2);

    float inv0 = 1.0f / l0, inv1 = 1.0f / l1;
    size_t r0g = ((size_t)(h * BB + b) * SS + q0 + wrow + g) * 64;
    size_t r1g = r0g + 8 * 64;
    #pragma unroll
    for (int nf = 0; nf < 8; ++nf) {
        int col = nf * 8 + qr * 2;
        *(__half2*)&Xh[r0g + col] = __floats2half2_rn(o[nf][0] * inv0, o[nf][1] * inv0);
        *(__half2*)&Xh[r1g + col] = __floats2half2_rn(o[nf][2] * inv1, o[nf][3] * inv1);
    }
}

extern "C" void kernel_launch(void* const* d_in, const int* in_sizes, int n_in,
                              void* d_out, int out_size)
{
    const float* q  = (const float*)d_in[0];
    const float* k  = (const float*)d_in[1];
    const float* v  = (const float*)d_in[2];
    const float* wq = (const float*)d_in[3];
    const float* bq = (const float*)d_in[4];
    const float* wk = (const float*)d_in[5];
    const float* bk = (const float*)d_in[6];
    const float* wv = (const float*)d_in[7];
    const float* bv = (const float*)d_in[8];
    const float* wo = (const float*)d_in[9];
    const float* bo = (const float*)d_in[10];
    float* out = (float*)d_out;

    __nv_bfloat16 *Whi, *Wlo, *Ahi, *Alo, *Qhi, *Qlo, *Khi, *Klo;
    __half *Vh, *Xh;
    cudaGetSymbolAddress((void**)&Whi, g_Whi);
    cudaGetSymbolAddress((void**)&Wlo, g_Wlo);
    cudaGetSymbolAddress((void**)&Ahi, g_Ahi);
    cudaGetSymbolAddress((void**)&Alo, g_Alo);
    cudaGetSymbolAddress((void**)&Qhi, g_Qhi);
    cudaGetSymbolAddress((void**)&Qlo, g_Qlo);
    cudaGetSymbolAddress((void**)&Khi, g_Khi);
    cudaGetSymbolAddress((void**)&Klo, g_Klo);
    cudaGetSymbolAddress((void**)&Vh,  g_Vh);
    cudaGetSymbolAddress((void**)&Xh,  g_Xh16);

    cudaFuncSetAttribute(qkv_gemm,    cudaFuncAttributeMaxDynamicSharedMemorySize, GEMM_SMEM);
    cudaFuncSetAttribute(out_gemm,    cudaFuncAttributeMaxDynamicSharedMemorySize, OUT_SMEM);
    cudaFuncSetAttribute(attn_kernel, cudaFuncAttributeMaxDynamicSharedMemorySize, ATTN_SMEM);

    dim3 pGrid(MTOT * DD / 4 / 256, 1, 4);
    pre_kernel<<<pGrid, 256>>>(q, k, v, wq, wk, wv, wo, Ahi, Alo, Whi, Wlo);

    dim3 qkvGrid(24, MTOT / 128);
    qkv_gemm<<<qkvGrid, 256, GEMM_SMEM>>>(Ahi, Alo, Whi, Wlo, bq, bk, bv,
                                          Qhi, Qlo, Khi, Klo, Vh);

    dim3 aGrid(SS / 128, BB * HH);
    attn_kernel<<<aGrid, 256, ATTN_SMEM>>>(Qhi, Qlo, Khi, Klo, Vh, Xh);

    dim3 oGrid(DD / 128, MTOT / 128);
    out_gemm<<<oGrid, 256, OUT_SMEM>>>(Xh, (const __half*)(Whi + 3*(size_t)DD*DD),
                                       bo, out);
}

// round 17
// speedup vs baseline: 1.1731x; 1.0086x over previous
#include <cuda_runtime.h>
#include <cuda_bf16.h>
#include <cuda_fp16.h>
#include <cstdint>
#include <math.h>

#define BB 2
#define SS 2048
#define DD 1024
#define HH 16
#define DHH 64
#define MTOT (BB*SS)
#define LOG2E 1.44269504088896f

// Whi plane 2 = Wv fp16, plane 3 = Wo fp16. Ahi plane 2 = v act fp16 (single).
__device__ __align__(256) __nv_bfloat16 g_Whi[4][DD*DD];
__device__ __align__(256) __nv_bfloat16 g_Wlo[2][DD*DD];
__device__ __align__(256) __nv_bfloat16 g_Ahi[3][MTOT*DD];
__device__ __align__(256) __nv_bfloat16 g_Alo[2][MTOT*DD];
__device__ __align__(256) __nv_bfloat16 g_Qhi[MTOT*DD];
__device__ __align__(256) __nv_bfloat16 g_Qlo[MTOT*DD];
__device__ __align__(256) __nv_bfloat16 g_Khi[MTOT*DD];
__device__ __align__(256) __nv_bfloat16 g_Klo[MTOT*DD];
__device__ __align__(256) __half        g_Vh [MTOT*DD];
__device__ __align__(256) __half        g_Xh16[MTOT*DD];

__device__ __forceinline__ uint32_t smem_u32(const void* p) {
    uint32_t a;
    asm("{ .reg .u64 t; cvta.to.shared.u64 t, %1; cvt.u32.u64 %0, t; }" : "=r"(a) : "l"(p));
    return a;
}
__device__ __forceinline__ void cp_async16(uint32_t dst, const void* src) {
    asm volatile("cp.async.cg.shared.global [%0], [%1], 16;" :: "r"(dst), "l"(src));
}
#define CP_COMMIT() asm volatile("cp.async.commit_group;" ::: "memory")

#define MMA_BF16(c, a, b0, b1) \
    asm volatile("mma.sync.aligned.m16n8k16.row.col.f32.bf16.bf16.f32 " \
        "{%0,%1,%2,%3}, {%4,%5,%6,%7}, {%8,%9}, {%0,%1,%2,%3};" \
        : "+f"((c)[0]), "+f"((c)[1]), "+f"((c)[2]), "+f"((c)[3]) \
        : "r"((a)[0]), "r"((a)[1]), "r"((a)[2]), "r"((a)[3]), "r"(b0), "r"(b1))

#define MMA_F16(c, a0, a1, a2, a3, b0, b1) \
    asm volatile("mma.sync.aligned.m16n8k16.row.col.f32.f16.f16.f32 " \
        "{%0,%1,%2,%3}, {%4,%5,%6,%7}, {%8,%9}, {%0,%1,%2,%3};" \
        : "+f"((c)[0]), "+f"((c)[1]), "+f"((c)[2]), "+f"((c)[3]) \
        : "r"(a0), "r"(a1), "r"(a2), "r"(a3), "r"(b0), "r"(b1))

#define LDM_X4(r, a) \
    asm volatile("ldmatrix.sync.aligned.m8n8.x4.shared.b16 {%0,%1,%2,%3}, [%4];" \
        : "=r"((r)[0]), "=r"((r)[1]), "=r"((r)[2]), "=r"((r)[3]) : "r"(a))

__device__ __forceinline__ uint32_t f2h2(float x, float y) {
    __half2 t = __floats2half2_rn(x, y);
    return *(uint32_t*)&t;
}
__device__ __forceinline__ float ex2(float x) {
    float y;
    asm("ex2.approx.ftz.f32 %0, %1;" : "=f"(y) : "f"(x));
    return y;
}

// ============ fused prologue ============
// z==0,1: bf16 hi/lo split of q,k (MLP-4). z==2: fp16 convert of v (MLP-4).
// z==3: weight transposes; wsel 0,1 bf16 hi/lo; wsel 2 (Wv), 3 (Wo) single fp16.
#define N4   (MTOT*DD/4)      // 1048576 float4s per tensor
#define NTH  (N4/4)           // 262144 threads per tensor (4 float4 each)

__global__ __launch_bounds__(256) void pre_kernel(
    const float* __restrict__ a0, const float* __restrict__ a1,
    const float* __restrict__ a2,
    const float* __restrict__ w0, const float* __restrict__ w1,
    const float* __restrict__ w2, const float* __restrict__ w3,
    __nv_bfloat16* __restrict__ Ahi_base, __nv_bfloat16* __restrict__ Alo_base,
    __nv_bfloat16* __restrict__ Whi_base, __nv_bfloat16* __restrict__ Wlo_base)
{
    if (blockIdx.z < 3) {
        if (blockIdx.x >= NTH / 256) return;
        int t = blockIdx.x * 256 + threadIdx.x;    // 0..NTH-1
        const float* a = (blockIdx.z == 0) ? a0 : (blockIdx.z == 1) ? a1 : a2;
        // 4 grid-strided float4 loads in flight (MLP 4)
        float4 v[4];
        #pragma unroll
        for (int j = 0; j < 4; ++j)
            v[j] = ((const float4*)a)[t + j * NTH];
        if (blockIdx.z == 2) {
            __half* a16 = (__half*)(Ahi_base + 2 * (size_t)MTOT * DD);
            #pragma unroll
            for (int j = 0; j < 4; ++j) {
                int i = t + j * NTH;
                ((__half2*)a16)[i*2+0] = __floats2half2_rn(v[j].x, v[j].y);
                ((__half2*)a16)[i*2+1] = __floats2half2_rn(v[j].z, v[j].w);
            }
        } else {
            __nv_bfloat16* hi = Ahi_base + (size_t)blockIdx.z * MTOT * DD;
            __nv_bfloat16* lo = Alo_base + (size_t)blockIdx.z * MTOT * DD;
            #pragma unroll
            for (int j = 0; j < 4; ++j) {
                int i = t + j * NTH;
                __nv_bfloat16 hx = __float2bfloat16_rn(v[j].x), hy = __float2bfloat16_rn(v[j].y);
                __nv_bfloat16 hz = __float2bfloat16_rn(v[j].z), hw = __float2bfloat16_rn(v[j].w);
                __nv_bfloat162 h0; h0.x = hx; h0.y = hy;
                __nv_bfloat162 h1; h1.x = hz; h1.y = hw;
                __nv_bfloat162 l0, l1;
                l0.x = __float2bfloat16_rn(v[j].x - __bfloat162float(hx));
                l0.y = __float2bfloat16_rn(v[j].y - __bfloat162float(hy));
                l1.x = __float2bfloat16_rn(v[j].z - __bfloat162float(hz));
                l1.y = __float2bfloat16_rn(v[j].w - __bfloat162float(hw));
                ((__nv_bfloat162*)hi)[i*2+0] = h0; ((__nv_bfloat162*)hi)[i*2+1] = h1;
                ((__nv_bfloat162*)lo)[i*2+0] = l0; ((__nv_bfloat162*)lo)[i*2+1] = l1;
            }
        }
    } else {
        int wsel = blockIdx.x >> 10;
        int tile = blockIdx.x & 1023;
        int bx = tile & 31, by = tile >> 5;
        const float* in = (wsel == 0) ? w0 : (wsel == 1) ? w1 : (wsel == 2) ? w2 : w3;
        __shared__ float t[32][33];
        int tx = threadIdx.x & 31, ty = threadIdx.x >> 5;
        int x = bx * 32 + tx;
        int y = by * 32 + ty;
        #pragma unroll
        for (int j = 0; j < 32; j += 8)
            t[ty + j][tx] = in[(size_t)(y + j) * DD + x];
        __syncthreads();
        int x2 = by * 32 + tx;
        int y2 = bx * 32 + ty;
        if (wsel >= 2) {
            __half* w16 = (__half*)(Whi_base + (size_t)wsel * DD * DD);
            #pragma unroll
            for (int j = 0; j < 32; j += 8)
                w16[(size_t)(y2 + j) * DD + x2] = __float2half_rn(t[tx][ty + j]);
        } else {
            __nv_bfloat16* hi = Whi_base + (size_t)wsel * DD * DD;
            __nv_bfloat16* lo = Wlo_base + (size_t)wsel * DD * DD;
            #pragma unroll
            for (int j = 0; j < 32; j += 8) {
                float w = t[tx][ty + j];
                __nv_bfloat16 h = __float2bfloat16_rn(w);
                hi[(size_t)(y2 + j) * DD + x2] = h;
                lo[(size_t)(y2 + j) * DD + x2] = __float2bfloat16_rn(w - __bfloat162float(h));
            }
        }
    }
}

// ============ fused QKV GEMM: 128x128, 3-stage, occ 2 ============
// proj 0,1: split-bf16 x split-bf16 (3 MMAs). proj 2: fp16 x fp16 (1 MMA).
#define T_AH    0
#define T_AL    8192
#define T_BH    16384
#define T_BL    24576
#define STAGE   32768
#define GEMM_SMEM (3*STAGE)

__device__ __forceinline__ void load_chunk_g(
    uint32_t sbase, int st,
    const __nv_bfloat16* __restrict__ Ah, const __nv_bfloat16* __restrict__ Al,
    const __nv_bfloat16* __restrict__ Bh, const __nv_bfloat16* __restrict__ Bl,
    int bm, int bn, int k0, int tid, bool full)
{
    uint32_t s = sbase + st * STAGE;
    #pragma unroll
    for (int it = 0; it < 2; ++it) {
        int idx = tid + it * 256;
        int row = idx >> 2, q = idx & 3;
        int qs = q ^ ((row >> 1) & 3);
        uint32_t doff = (uint32_t)(row * 64 + qs * 16);
        size_t ga = (size_t)(bm + row) * DD + k0 + q * 8;
        size_t gb = (size_t)(bn + row) * DD + k0 + q * 8;
        cp_async16(s + T_AH + doff, Ah + ga);
        cp_async16(s + T_BH + doff, Bh + gb);
        if (full) {
            cp_async16(s + T_AL + doff, Al + ga);
            cp_async16(s + T_BL + doff, Bl + gb);
        }
    }
    CP_COMMIT();
}

__global__ __launch_bounds__(256, 2) void qkv_gemm(
    const __nv_bfloat16* __restrict__ Ahi_all, const __nv_bfloat16* __restrict__ Alo_all,
    const __nv_bfloat16* __restrict__ Whi_all, const __nv_bfloat16* __restrict__ Wlo_all,
    const float* __restrict__ bq, const float* __restrict__ bk, const float* __restrict__ bv,
    __nv_bfloat16* __restrict__ Qhi, __nv_bfloat16* __restrict__ Qlo,
    __nv_bfloat16* __restrict__ Khi, __nv_bfloat16* __restrict__ Klo,
    __half* __restrict__ Vh)
{
    extern __shared__ char smem[];
    const uint32_t sbase = smem_u32(smem);
    const int tid = threadIdx.x, wid = tid >> 5, lane = tid & 31;
    const int warp_m = wid & 1, warp_n = wid >> 1;
    const int proj = blockIdx.x >> 3;
    const int bn = (blockIdx.x & 7) * 128;
    const int bm = blockIdx.y * 128;
    const bool isV = (proj == 2);

    const __nv_bfloat16* Ah = Ahi_all + (size_t)proj * MTOT * DD;
    const __nv_bfloat16* Al = Alo_all + (size_t)(isV ? 0 : proj) * MTOT * DD;
    const __nv_bfloat16* Bh = Whi_all + (size_t)proj * DD * DD;
    const __nv_bfloat16* Bl = Wlo_all + (size_t)(isV ? 0 : proj) * DD * DD;
    const float* bias = (proj == 0) ? bq : (proj == 1) ? bk : bv;
    const float oscale = (proj == 0) ? LOG2E : 1.0f;

    const int a_row = warp_m * 64 + (lane & 15);
    const int sA = (a_row >> 1) & 3;
    const int b_row = warp_n * 32 + ((lane >> 4) << 3) + (lane & 7);
    const int sB = (b_row >> 1) & 3;
    const int ca = (lane >> 4);
    const int cb = ((lane >> 3) & 1);

    float c[4][4][4];
    #pragma unroll
    for (int i = 0; i < 4; ++i)
        #pragma unroll
        for (int j = 0; j < 4; ++j)
            #pragma unroll
            for (int e = 0; e < 4; ++e) c[i][j][e] = 0.f;

    load_chunk_g(sbase, 0, Ah, Al, Bh, Bl, bm, bn, 0,  tid, !isV);
    load_chunk_g(sbase, 1, Ah, Al, Bh, Bl, bm, bn, 32, tid, !isV);

    const int NCHUNK = DD / 32;
    for (int i = 0; i < NCHUNK; ++i) {
        const int st = i % 3;
        if (i < NCHUNK - 1) asm volatile("cp.async.wait_group 1;" ::: "memory");
        else                asm volatile("cp.async.wait_group 0;" ::: "memory");
        __syncthreads();
        if (i + 2 < NCHUNK)
            load_chunk_g(sbase, (i + 2) % 3, Ah, Al, Bh, Bl, bm, bn, (i + 2) * 32, tid, !isV);

        const uint32_t stb = sbase + st * STAGE;
        #pragma unroll
        for (int ks = 0; ks < 2; ++ks) {
            uint32_t ah[4][4], al[4][4], bh[2][4], bl[2][4];
            const uint32_t ac = (uint32_t)(((ks * 2 + ca) ^ sA) << 4);
            const uint32_t bc = (uint32_t)(((ks * 2 + cb) ^ sB) << 4);
            #pragma unroll
            for (int mf = 0; mf < 4; ++mf) {
                uint32_t ra = stb + T_AH + (uint32_t)((a_row + mf * 16) * 64) + ac;
                LDM_X4(ah[mf], ra);
                if (!isV) LDM_X4(al[mf], ra + (T_AL - T_AH));
            }
            #pragma unroll
            for (int p = 0; p < 2; ++p) {
                uint32_t rb = stb + T_BH + (uint32_t)((b_row + p * 16) * 64) + bc;
                LDM_X4(bh[p], rb);
                if (!isV) LDM_X4(bl[p], rb + (T_BL - T_BH));
            }
            if (!isV) {
                #pragma unroll
                for (int mf = 0; mf < 4; ++mf)
                    #pragma unroll
                    for (int nf = 0; nf < 4; ++nf) {
                        const int p = nf >> 1, hh = (nf & 1) * 2;
                        MMA_BF16(c[mf][nf], ah[mf], bh[p][hh], bh[p][hh+1]);
                        MMA_BF16(c[mf][nf], ah[mf], bl[p][hh], bl[p][hh+1]);
                        MMA_BF16(c[mf][nf], al[mf], bh[p][hh], bh[p][hh+1]);
                    }
            } else {
                #pragma unroll
                for (int mf = 0; mf < 4; ++mf)
                    #pragma unroll
                    for (int nf = 0; nf < 4; ++nf) {
                        const int p = nf >> 1, hh = (nf & 1) * 2;
                        MMA_F16(c[mf][nf], ah[mf][0], ah[mf][1], ah[mf][2], ah[mf][3],
                                bh[p][hh], bh[p][hh+1]);
                    }
            }
        }
    }

    __nv_bfloat16* Oh = (proj == 0) ? Qhi : Khi;
    __nv_bfloat16* Ol = (proj == 0) ? Qlo : Klo;

    #pragma unroll
    for (int mf = 0; mf < 4; ++mf) {
        int m0 = bm + warp_m * 64 + mf * 16 + (lane >> 2);
        #pragma unroll
        for (int nf = 0; nf < 4; ++nf) {
            int n = bn + warp_n * 32 + nf * 8 + (lane & 3) * 2;
            float2 bb = *(const float2*)&bias[n];
            float v0 = (c[mf][nf][0] + bb.x) * oscale, v1 = (c[mf][nf][1] + bb.y) * oscale;
            float v2 = (c[mf][nf][2] + bb.x) * oscale, v3 = (c[mf][nf][3] + bb.y) * oscale;
            size_t i0 = (size_t)m0 * DD + n, i1 = (size_t)(m0 + 8) * DD + n;
            if (isV) {
                *(__half2*)&Vh[i0] = __floats2half2_rn(v0, v1);
                *(__half2*)&Vh[i1] = __floats2half2_rn(v2, v3);
            } else {
                __nv_bfloat16 h0 = __float2bfloat16_rn(v0), h1 = __float2bfloat16_rn(v1);
                __nv_bfloat16 h2 = __float2bfloat16_rn(v2), h3 = __float2bfloat16_rn(v3);
                __nv_bfloat162 H0; H0.x = h0; H0.y = h1;
                __nv_bfloat162 H1; H1.x = h2; H1.y = h3;
                __nv_bfloat162 L0, L1;
                L0.x = __float2bfloat16_rn(v0 - __bfloat162float(h0));
                L0.y = __float2bfloat16_rn(v1 - __bfloat162float(h1));
                L1.x = __float2bfloat16_rn(v2 - __bfloat162float(h2));
                L1.y = __float2bfloat16_rn(v3 - __bfloat162float(h3));
                *(__nv_bfloat162*)&Oh[i0] = H0; *(__nv_bfloat162*)&Oh[i1] = H1;
                *(__nv_bfloat162*)&Ol[i0] = L0; *(__nv_bfloat162*)&Ol[i1] = L1;
            }
        }
    }
}

// ============ fp16 1-MMA out GEMM: 4-stage pipeline ============
#define O_A  0
#define O_B  8192
#define O_STAGE 16384
#define OUT_SMEM (4*O_STAGE)   // 65536

__device__ __forceinline__ void load_chunk_o(
    uint32_t sbase, int st,
    const __half* __restrict__ Xh, const __half* __restrict__ W16,
    int bm, int bn, int k0, int tid)
{
    uint32_t s = sbase + st * O_STAGE;
    #pragma unroll
    for (int it = 0; it < 2; ++it) {
        int idx = tid + it * 256;
        int row = idx >> 2, q = idx & 3;
        int qs = q ^ ((row >> 1) & 3);
        uint32_t doff = (uint32_t)(row * 64 + qs * 16);
        size_t ga = (size_t)(bm + row) * DD + k0 + q * 8;
        size_t gb = (size_t)(bn + row) * DD + k0 + q * 8;
        cp_async16(s + O_A + doff, Xh + ga);
        cp_async16(s + O_B + doff, W16 + gb);
    }
    CP_COMMIT();
}

__global__ __launch_bounds__(256, 2) void out_gemm(
    const __half* __restrict__ Xh, const __half* __restrict__ W16,
    const float* __restrict__ bias, float* __restrict__ C)
{
    extern __shared__ char smem[];
    const uint32_t sbase = smem_u32(smem);
    const int tid = threadIdx.x, wid = tid >> 5, lane = tid & 31;
    const int warp_m = wid & 1, warp_n = wid >> 1;
    const int bm = blockIdx.y * 128, bn = blockIdx.x * 128;

    const int a_row = warp_m * 64 + (lane & 15);
    const int sA = (a_row >> 1) & 3;
    const int b_row = warp_n * 32 + ((lane >> 4) << 3) + (lane & 7);
    const int sB = (b_row >> 1) & 3;
    const int ca = (lane >> 4);
    const int cb = ((lane >> 3) & 1);

    float c[4][4][4];
    #pragma unroll
    for (int i = 0; i < 4; ++i)
        #pragma unroll
        for (int j = 0; j < 4; ++j)
            #pragma unroll
            for (int e = 0; e < 4; ++e) c[i][j][e] = 0.f;

    load_chunk_o(sbase, 0, Xh, W16, bm, bn, 0,  tid);
    load_chunk_o(sbase, 1, Xh, W16, bm, bn, 32, tid);
    load_chunk_o(sbase, 2, Xh, W16, bm, bn, 64, tid);

    const int NCHUNK = DD / 32;
    for (int i = 0; i < NCHUNK; ++i) {
        const int st = i & 3;
        const int pend = NCHUNK - 1 - i;
        if (pend >= 2)      asm volatile("cp.async.wait_group 2;" ::: "memory");
        else if (pend == 1) asm volatile("cp.async.wait_group 1;" ::: "memory");
        else                asm volatile("cp.async.wait_group 0;" ::: "memory");
        __syncthreads();
        if (i + 3 < NCHUNK)
            load_chunk_o(sbase, (i + 3) & 3, Xh, W16, bm, bn, (i + 3) * 32, tid);

        const uint32_t stb = sbase + st * O_STAGE;
        #pragma unroll
        for (int ks = 0; ks < 2; ++ks) {
            uint32_t ah[4][4], bh[2][4];
            const uint32_t ac = (uint32_t)(((ks * 2 + ca) ^ sA) << 4);
            const uint32_t bc = (uint32_t)(((ks * 2 + cb) ^ sB) << 4);
            #pragma unroll
            for (int mf = 0; mf < 4; ++mf) {
                uint32_t ra = stb + O_A + (uint32_t)((a_row + mf * 16) * 64) + ac;
                LDM_X4(ah[mf], ra);
            }
            #pragma unroll
            for (int p = 0; p < 2; ++p) {
                uint32_t rb = stb + O_B + (uint32_t)((b_row + p * 16) * 64) + bc;
                LDM_X4(bh[p], rb);
            }
            #pragma unroll
            for (int mf = 0; mf < 4; ++mf)
                #pragma unroll
                for (int nf = 0; nf < 4; ++nf) {
                    const int p = nf >> 1, hh = (nf & 1) * 2;
                    MMA_F16(c[mf][nf], ah[mf][0], ah[mf][1], ah[mf][2], ah[mf][3],
                            bh[p][hh], bh[p][hh+1]);
                }
        }
    }

    #pragma unroll
    for (int mf = 0; mf < 4; ++mf) {
        int m0 = bm + warp_m * 64 + mf * 16 + (lane >> 2);
        #pragma unroll
        for (int nf = 0; nf < 4; ++nf) {
            int n = bn + warp_n * 32 + nf * 8 + (lane & 3) * 2;
            float2 bb = *(const float2*)&bias[n];
            *(float2*)&C[(size_t)m0 * DD + n] =
                make_float2(c[mf][nf][0] + bb.x, c[mf][nf][1] + bb.y);
            *(float2*)&C[(size_t)(m0 + 8) * DD + n] =
                make_float2(c[mf][nf][2] + bb.x, c[mf][nf][3] + bb.y);
        }
    }
}

// ============ flash attention: 2-stage 128-key KV ring (stage0 overlays Q) ============
#define AKH 0
#define AKL 16384
#define AKV 32768
#define AST 49152
#define ATTN_SMEM (2*AST)

__device__ __forceinline__ void load_kv128(uint32_t stage_base,
    const char* Khb, const char* Klb, const char* Vhb, int key0, int tid)
{
    #pragma unroll
    for (int p = 0; p < 4; ++p) {
        int id = tid + p * 256;
        int row = id >> 3, c = id & 7;
        int cs = c ^ (row & 7);
        size_t go = (size_t)(key0 + row) * (DD * 2) + c * 16;
        uint32_t so = (uint32_t)(row * 128 + cs * 16);
        cp_async16(stage_base + AKH + so, Khb + go);
        cp_async16(stage_base + AKL + so, Klb + go);
        cp_async16(stage_base + AKV + so, Vhb + go);
    }
    CP_COMMIT();
}

__global__ __launch_bounds__(256, 2) void attn_kernel(
    const __nv_bfloat16* __restrict__ Qh, const __nv_bfloat16* __restrict__ Ql,
    const __nv_bfloat16* __restrict__ Kh, const __nv_bfloat16* __restrict__ Kl,
    const __half* __restrict__ Vv, __half* __restrict__ Xh)
{
    extern __shared__ char sm[];
    const uint32_t sb = smem_u32(sm);
    const int tid = threadIdx.x, lane = tid & 31, w = tid >> 5;
    const int q0 = blockIdx.x * 128;
    const int b = blockIdx.y >> 4, h = blockIdx.y & 15;
    const int g = lane >> 2, qr = lane & 3;
    const int wrow = w * 16;

    const char* Qhb = (const char*)(Qh + (size_t)b * SS * DD + h * 64);
    const char* Qlb = (const char*)(Ql + (size_t)b * SS * DD + h * 64);
    const char* Khb = (const char*)(Kh + (size_t)b * SS * DD + h * 64);
    const char* Klb = (const char*)(Kl + (size_t)b * SS * DD + h * 64);
    const char* Vhb = (const char*)(Vv + (size_t)b * SS * DD + h * 64);

    #pragma unroll
    for (int p = 0; p < 4; ++p) {
        int id = tid + p * 256;
        int row = id >> 3, c = id & 7;
        int cs = c ^ (row & 7);
        size_t go = (size_t)(q0 + row) * (DD * 2) + c * 16;
        uint32_t so = (uint32_t)(row * 128 + cs * 16);
        cp_async16(sb + 0 + so, Qhb + go);
        cp_async16(sb + 16384 + so, Qlb + go);
    }
    CP_COMMIT();

    asm volatile("cp.async.wait_group 0;" ::: "memory");
    __syncthreads();
    const int q_row = wrow + (lane & 15);
    const int kq = q_row & 7;
    const int ca = lane >> 4;
    uint32_t qh[4][4], ql[4][4];
    #pragma unroll
    for (int kc = 0; kc < 4; ++kc) {
        uint32_t ra = sb + (uint32_t)(q_row * 128 + (((kc * 2 + ca) ^ kq) << 4));
        LDM_X4(qh[kc], ra);
        LDM_X4(ql[kc], ra + 16384);
    }
    __syncthreads();
    load_kv128(sb, Khb, Klb, Vhb, 0, tid);

    const int k_rowb = ((lane >> 4) << 3) + (lane & 7);
    const int kk = lane & 7;
    const int cb = (lane >> 3) & 1;
    const int v_row = (((lane >> 3) & 1) << 3) + (lane & 7);
    const int kv_key = lane & 7;
    const int cv = lane >> 4;

    float m0 = -1e30f, m1 = -1e30f, l0 = 0.f, l1 = 0.f;
    float o[8][4];
    #pragma unroll
    for (int j = 0; j < 8; ++j)
        #pragma unroll
        for (int e = 0; e < 4; ++e) o[j][e] = 0.f;

    const int NK = SS / 128;
    for (int kt = 0; kt < NK; ++kt) {
        asm volatile("cp.async.wait_group 0;" ::: "memory");
        __syncthreads();
        if (kt + 1 < NK)
            load_kv128(sb + (uint32_t)(((kt + 1) & 1) * AST),
                       Khb, Klb, Vhb, (kt + 1) * 128, tid);

        const uint32_t STb = sb + (uint32_t)((kt & 1) * AST);

        #pragma unroll
        for (int half = 0; half < 2; ++half) {
            const int rbase = half * 64;

            float s[8][4];
            #pragma unroll
            for (int j = 0; j < 8; ++j)
                #pragma unroll
                for (int e = 0; e < 4; ++e) s[j][e] = 0.f;

            #pragma unroll
            for (int kc = 0; kc < 4; ++kc) {
                const uint32_t kcol = (uint32_t)((((kc * 2 + cb) ^ kk) << 4));
                #pragma unroll
                for (int p = 0; p < 4; ++p) {
                    uint32_t rb = STb + AKH
                        + (uint32_t)((rbase + k_rowb + p * 16) * 128) + kcol;
                    uint32_t kh4[4], kl4[4];
                    LDM_X4(kh4, rb);
                    LDM_X4(kl4, rb + (AKL - AKH));
                    MMA_BF16(s[2*p],   qh[kc], kh4[0], kh4[1]);
                    MMA_BF16(s[2*p],   qh[kc], kl4[0], kl4[1]);
                    MMA_BF16(s[2*p],   ql[kc], kh4[0], kh4[1]);
                    MMA_BF16(s[2*p+1], qh[kc], kh4[2], kh4[3]);
                    MMA_BF16(s[2*p+1], qh[kc], kl4[2], kl4[3]);
                    MMA_BF16(s[2*p+1], ql[kc], kh4[2], kh4[3]);
                }
            }

            float mx0 = -1e30f, mx1 = -1e30f;
            #pragma unroll
            for (int j = 0; j < 8; ++j) {
                mx0 = fmaxf(mx0, fmaxf(s[j][0], s[j][1]));
                mx1 = fmaxf(mx1, fmaxf(s[j][2], s[j][3]));
            }
            mx0 = fmaxf(mx0, __shfl_xor_sync(0xffffffffu, mx0, 1));
            mx0 = fmaxf(mx0, __shfl_xor_sync(0xffffffffu, mx0, 2));
            mx1 = fmaxf(mx1, __shfl_xor_sync(0xffffffffu, mx1, 1));
            mx1 = fmaxf(mx1, __shfl_xor_sync(0xffffffffu, mx1, 2));
            float m0n = fmaxf(m0, mx0), m1n = fmaxf(m1, mx1);
            bool nore = __all_sync(0xffffffffu, (m0n == m0) && (m1n == m1));
            if (!nore) {
                float sc0 = ex2(m0 - m0n), sc1 = ex2(m1 - m1n);
                l0 *= sc0; l1 *= sc1;
                #pragma unroll
                for (int j = 0; j < 8; ++j) {
                    o[j][0] *= sc0; o[j][1] *= sc0;
                    o[j][2] *= sc1; o[j][3] *= sc1;
                }
            }
            m0 = m0n; m1 = m1n;

            const uint32_t vbase = STb + AKV;
            #pragma unroll
            for (int kc = 0; kc < 4; ++kc) {
                const int j0 = 2 * kc, j1 = 2 * kc + 1;
                float e00 = ex2(s[j0][0] - m0n), e01 = ex2(s[j0][1] - m0n);
                float e02 = ex2(s[j0][2] - m1n), e03 = ex2(s[j0][3] - m1n);
                float e10 = ex2(s[j1][0] - m0n), e11 = ex2(s[j1][1] - m0n);
                float e12 = ex2(s[j1][2] - m1n), e13 = ex2(s[j1][3] - m1n);
                l0 += e00 + e01 + e10 + e11;
                l1 += e02 + e03 + e12 + e13;
                uint32_t a0 = f2h2(e00, e01);
                uint32_t a1 = f2h2(e02, e03);
                uint32_t a2 = f2h2(e10, e11);
                uint32_t a3 = f2h2(e12, e13);
                const int mrow = rbase + kc * 16 + v_row;
                #pragma unroll
                for (int nfp = 0; nfp < 4; ++nfp) {
                    const int nf = 2 * nfp;
                    uint32_t addr = vbase + (uint32_t)(mrow * 128
                                     + (((nf + cv) ^ kv_key) << 4));
                    uint32_t r0, r1, r2, r3;
                    asm volatile("ldmatrix.sync.aligned.m8n8.x4.trans.shared.b16 {%0,%1,%2,%3}, [%4];"
                        : "=r"(r0), "=r"(r1), "=r"(r2), "=r"(r3) : "r"(addr));
                    MMA_F16(o[nf],     a0, a1, a2, a3, r0, r1);
                    MMA_F16(o[nf + 1], a0, a1, a2, a3, r2, r3);
                }
            }
        }
    }

    l0 += __shfl_xor_sync(0xffffffffu, l0, 1);
    l0 += __shfl_xor_sync(0xffffffffu, l0, 2);
    l1 += __shfl_xor_sync(0xffffffffu, l1, 1);
    l1 += __shfl_xor_sync(0xffffffffu, l1, 2);

    float inv0 = 1.0f / l0, inv1 = 1.0f / l1;
    size_t r0g = ((size_t)(h * BB + b) * SS + q0 + wrow + g) * 64;
    size_t r1g = r0g + 8 * 64;
    #pragma unroll
    for (int nf = 0; nf < 8; ++nf) {
        int col = nf * 8 + qr * 2;
        *(__half2*)&Xh[r0g + col] = __floats2half2_rn(o[nf][0] * inv0, o[nf][1] * inv0);
        *(__half2*)&Xh[r1g + col] = __floats2half2_rn(o[nf][2] * inv1, o[nf][3] * inv1);
    }
}

extern "C" void kernel_launch(void* const* d_in, const int* in_sizes, int n_in,
                              void* d_out, int out_size)
{
    const float* q  = (const float*)d_in[0];
    const float* k  = (const float*)d_in[1];
    const float* v  = (const float*)d_in[2];
    const float* wq = (const float*)d_in[3];
    const float* bq = (const float*)d_in[4];
    const float* wk = (const float*)d_in[5];
    const float* bk = (const float*)d_in[6];
    const float* wv = (const float*)d_in[7];
    const float* bv = (const float*)d_in[8];
    const float* wo = (const float*)d_in[9];
    const float* bo = (const float*)d_in[10];
    float* out = (float*)d_out;

    __nv_bfloat16 *Whi, *Wlo, *Ahi, *Alo, *Qhi, *Qlo, *Khi, *Klo;
    __half *Vh, *Xh;
    cudaGetSymbolAddress((void**)&Whi, g_Whi);
    cudaGetSymbolAddress((void**)&Wlo, g_Wlo);
    cudaGetSymbolAddress((void**)&Ahi, g_Ahi);
    cudaGetSymbolAddress((void**)&Alo, g_Alo);
    cudaGetSymbolAddress((void**)&Qhi, g_Qhi);
    cudaGetSymbolAddress((void**)&Qlo, g_Qlo);
    cudaGetSymbolAddress((void**)&Khi, g_Khi);
    cudaGetSymbolAddress((void**)&Klo, g_Klo);
    cudaGetSymbolAddress((void**)&Vh,  g_Vh);
    cudaGetSymbolAddress((void**)&Xh,  g_Xh16);

    cudaFuncSetAttribute(qkv_gemm,    cudaFuncAttributeMaxDynamicSharedMemorySize, GEMM_SMEM);
    cudaFuncSetAttribute(out_gemm,    cudaFuncAttributeMaxDynamicSharedMemorySize, OUT_SMEM);
    cudaFuncSetAttribute(attn_kernel, cudaFuncAttributeMaxDynamicSharedMemorySize, ATTN_SMEM);

    dim3 pGrid(4096, 1, 4);
    pre_kernel<<<pGrid, 256>>>(q, k, v, wq, wk, wv, wo, Ahi, Alo, Whi, Wlo);

    dim3 qkvGrid(24, MTOT / 128);
    qkv_gemm<<<qkvGrid, 256, GEMM_SMEM>>>(Ahi, Alo, Whi, Wlo, bq, bk, bv,
                                          Qhi, Qlo, Khi, Klo, Vh);

    dim3 aGrid(SS / 128, BB * HH);
    attn_kernel<<<aGrid, 256, ATTN_SMEM>>>(Qhi, Qlo, Khi, Klo, Vh, Xh);

    dim3 oGrid(DD / 128, MTOT / 128);
    out_gemm<<<oGrid, 256, OUT_SMEM>>>(Xh, (const __half*)(Whi + 3*(size_t)DD*DD),
                                       bo, out);
}